// round 9
// baseline (speedup 1.0000x reference)
#include <cuda_runtime.h>
#include <cuda_fp16.h>
#include <math.h>
#include <stdint.h>

// ---------------- problem dims ----------------
#define BB   2
#define TQc  32
#define NQc  196
#define DQ   896
#define NQT  6272
#define MQ   12544
#define NKT  2048
#define MKV  4096
#define CIN  4
#define EMB  1024
#define HID  512
#define NH   4
#define HD   128
#define FFD  1024
#define OUTD 896
#define NSPLIT 2
#define TILES_PER_SPLIT (NKT / 64 / NSPLIT)   // 16

// ---------------- scratch ----------------
__device__ float g_qin[(size_t)MQ * HID];
__device__ float g_kv [(size_t)MKV * EMB];
__device__ float g_q  [(size_t)MQ * HID];
__device__ float g_k  [(size_t)MKV * HID];
__device__ float g_v  [(size_t)MKV * HID];
__device__ float g_o  [(size_t)MQ * HID];
__device__ float g_h  [(size_t)MQ * HID];
__device__ float g_ff [(size_t)MQ * FFD];
__device__ float g_h2 [(size_t)MQ * HID];
__device__ float g_vt [(size_t)BB * NH * HD * NKT];
__device__ float g_op [(size_t)NSPLIT * MQ * HID];      // split partial O
__device__ float g_pm [(size_t)NSPLIT * BB * NH * NQT]; // split row max
__device__ float g_pl [(size_t)NSPLIT * BB * NH * NQT]; // split row sum
// transposed weights [N,K]
__device__ float g_wqinT[512 * 896];
__device__ float g_wqT  [512 * 512];
__device__ float g_wkT  [512 * 1024];
__device__ float g_wvT  [512 * 1024];
__device__ float g_woT  [512 * 512];
__device__ float g_w1T  [1024 * 512];
__device__ float g_w2T  [512 * 1024];
__device__ float g_m1T  [1024 * 512];
__device__ float g_m2T  [896 * 1024];

// ---------------- fp16 helpers ----------------
__device__ __forceinline__ uint32_t f2h2(float a, float b)
{
    __half2 h = __float22half2_rn(make_float2(a, b));
    return *(uint32_t*)&h;
}

__device__ __forceinline__ void mma_f16(float* d, const uint32_t* a, const uint32_t* b)
{
    asm volatile(
        "mma.sync.aligned.m16n8k16.row.col.f32.f16.f16.f32 "
        "{%0,%1,%2,%3}, {%4,%5,%6,%7}, {%8,%9}, {%0,%1,%2,%3};\n"
        : "+f"(d[0]), "+f"(d[1]), "+f"(d[2]), "+f"(d[3])
        : "r"(a[0]), "r"(a[1]), "r"(a[2]), "r"(a[3]), "r"(b[0]), "r"(b[1]));
}

// =================================================================
// Fused flash attention, fp16 mma, split-KV.
// Grid (NQT/128, BB*NH, NSPLIT), 256 thr (8 warps x 16 q-rows).
// Each split covers 16 kv-tiles of 64; writes normalized partial O + m,l.
// =================================================================
#define FQ_W 68
#define FV_W 36
#define FLASH_WORDS (128*FQ_W + 64*FQ_W + 128*FV_W + 128*FV_W)
#define FLASH_SMEM (FLASH_WORDS * 4)   // 89088 B

__global__ void __launch_bounds__(256)
flash_attn(const float* __restrict__ gq, const float* __restrict__ gk,
           const float* __restrict__ gvt, float* __restrict__ op,
           float* __restrict__ pm, float* __restrict__ pl)
{
    extern __shared__ __align__(16) uint32_t sh[];
    uint32_t* Qs = sh;
    uint32_t* Ks = sh + 128 * FQ_W;
    uint32_t* Vs = Ks + 64 * FQ_W;
    uint32_t* Ps = Vs + 128 * FV_W;

    int bh = blockIdx.y;
    int b = bh >> 2, h = bh & 3;
    int hoff = h * HD;
    int split = blockIdx.z;
    long qrow0 = (long)b * NQT + (long)blockIdx.x * 128;
    long kvrow0 = (long)b * NKT;
    const float* vtbase = gvt + (size_t)bh * HD * NKT;

    int tid = threadIdx.x, w = tid >> 5, lane = tid & 31;
    int g = lane >> 2, tg = lane & 3;
    int wr = w * 16 + g;

    // ---- stage Q tile (128x128) as fp16 ----
    {
        int row = tid >> 1, fseg = (tid & 1) << 6;
        const float* src = gq + (qrow0 + row) * HID + hoff + fseg;
        uint32_t* dst = Qs + row * FQ_W + (fseg >> 1);
        #pragma unroll
        for (int i = 0; i < 8; i++) {
            float4 v0 = *(const float4*)(src + i * 8);
            float4 v1 = *(const float4*)(src + i * 8 + 4);
            uint4 u;
            u.x = f2h2(v0.x, v0.y); u.y = f2h2(v0.z, v0.w);
            u.z = f2h2(v1.x, v1.y); u.w = f2h2(v1.z, v1.w);
            *(uint4*)(dst + i * 4) = u;
        }
    }

    float Oacc[16][4];
    #pragma unroll
    for (int j = 0; j < 16; j++)
        #pragma unroll
        for (int c = 0; c < 4; c++) Oacc[j][c] = 0.f;
    float m0 = -1e30f, m1 = -1e30f, l0 = 0.f, l1 = 0.f;

    const float scale = 0.08838834764831845f;
    int kvr = tid >> 2, kfs = (tid & 3) << 5;
    int vr = tid >> 1, vfs = (tid & 1) << 5;

    int jt0 = split * TILES_PER_SPLIT;
    for (int jt = jt0; jt < jt0 + TILES_PER_SPLIT; jt++) {
        __syncthreads();
        {
            const float* ksrc = gk + (kvrow0 + jt * 64 + kvr) * HID + hoff + kfs;
            uint32_t* kd = Ks + kvr * FQ_W + (kfs >> 1);
            #pragma unroll
            for (int i = 0; i < 4; i++) {
                float4 v0 = *(const float4*)(ksrc + i * 8);
                float4 v1 = *(const float4*)(ksrc + i * 8 + 4);
                uint4 u;
                u.x = f2h2(v0.x, v0.y); u.y = f2h2(v0.z, v0.w);
                u.z = f2h2(v1.x, v1.y); u.w = f2h2(v1.z, v1.w);
                *(uint4*)(kd + i * 4) = u;
            }
            const float* vsrc = vtbase + (size_t)vr * NKT + jt * 64 + vfs;
            uint32_t* vd = Vs + vr * FV_W + (vfs >> 1);
            #pragma unroll
            for (int i = 0; i < 4; i++) {
                float4 v0 = *(const float4*)(vsrc + i * 8);
                float4 v1 = *(const float4*)(vsrc + i * 8 + 4);
                uint4 u;
                u.x = f2h2(v0.x, v0.y); u.y = f2h2(v0.z, v0.w);
                u.z = f2h2(v1.x, v1.y); u.w = f2h2(v1.z, v1.w);
                *(uint4*)(vd + i * 4) = u;
            }
        }
        __syncthreads();

        // ---- S = Q.K^T ----
        float S[8][4];
        #pragma unroll
        for (int j = 0; j < 8; j++)
            #pragma unroll
            for (int c = 0; c < 4; c++) S[j][c] = 0.f;
        {
            const uint32_t* Qw = Qs + wr * FQ_W;
            #pragma unroll
            for (int kk2 = 0; kk2 < 64; kk2 += 8) {
                uint32_t af[4];
                af[0] = Qw[kk2 + tg];
                af[1] = Qw[8 * FQ_W + kk2 + tg];
                af[2] = Qw[kk2 + tg + 4];
                af[3] = Qw[8 * FQ_W + kk2 + tg + 4];
                #pragma unroll
                for (int j = 0; j < 8; j++) {
                    const uint32_t* kb = Ks + (j * 8 + g) * FQ_W + kk2 + tg;
                    uint32_t bf[2] = { kb[0], kb[4] };
                    mma_f16(S[j], af, bf);
                }
            }
        }

        // ---- online softmax ----
        float mx0 = -1e30f, mx1 = -1e30f;
        #pragma unroll
        for (int j = 0; j < 8; j++) {
            #pragma unroll
            for (int c = 0; c < 4; c++) S[j][c] *= scale;
            mx0 = fmaxf(mx0, fmaxf(S[j][0], S[j][1]));
            mx1 = fmaxf(mx1, fmaxf(S[j][2], S[j][3]));
        }
        mx0 = fmaxf(mx0, __shfl_xor_sync(~0u, mx0, 1));
        mx0 = fmaxf(mx0, __shfl_xor_sync(~0u, mx0, 2));
        mx1 = fmaxf(mx1, __shfl_xor_sync(~0u, mx1, 1));
        mx1 = fmaxf(mx1, __shfl_xor_sync(~0u, mx1, 2));
        float mn0 = fmaxf(m0, mx0), mn1 = fmaxf(m1, mx1);
        float al0 = __expf(m0 - mn0), al1 = __expf(m1 - mn1);
        m0 = mn0; m1 = mn1;
        float sum0 = 0.f, sum1 = 0.f;
        uint32_t* prow0 = Ps + wr * FV_W;
        uint32_t* prow1 = Ps + (wr + 8) * FV_W;
        #pragma unroll
        for (int j = 0; j < 8; j++) {
            float p0 = __expf(S[j][0] - mn0);
            float p1 = __expf(S[j][1] - mn0);
            float p2 = __expf(S[j][2] - mn1);
            float p3 = __expf(S[j][3] - mn1);
            sum0 += p0 + p1; sum1 += p2 + p3;
            prow0[4 * j + tg] = f2h2(p0, p1);
            prow1[4 * j + tg] = f2h2(p2, p3);
        }
        sum0 += __shfl_xor_sync(~0u, sum0, 1);
        sum0 += __shfl_xor_sync(~0u, sum0, 2);
        sum1 += __shfl_xor_sync(~0u, sum1, 1);
        sum1 += __shfl_xor_sync(~0u, sum1, 2);
        l0 = l0 * al0 + sum0;
        l1 = l1 * al1 + sum1;
        #pragma unroll
        for (int j = 0; j < 16; j++) {
            Oacc[j][0] *= al0; Oacc[j][1] *= al0;
            Oacc[j][2] *= al1; Oacc[j][3] *= al1;
        }
        __syncwarp();

        // ---- O += P.V ----
        {
            const uint32_t* Pw = Ps + wr * FV_W;
            #pragma unroll
            for (int kk2 = 0; kk2 < 32; kk2 += 8) {
                uint32_t af[4];
                af[0] = Pw[kk2 + tg];
                af[1] = Pw[8 * FV_W + kk2 + tg];
                af[2] = Pw[kk2 + tg + 4];
                af[3] = Pw[8 * FV_W + kk2 + tg + 4];
                #pragma unroll
                for (int j2 = 0; j2 < 16; j2++) {
                    const uint32_t* vb = Vs + (j2 * 8 + g) * FV_W + kk2 + tg;
                    uint32_t bf[2] = { vb[0], vb[4] };
                    mma_f16(Oacc[j2], af, bf);
                }
            }
        }
        __syncwarp();
    }

    // ---- epilogue: normalized partial O + (m, l) per row ----
    float inv0 = 1.f / l0, inv1 = 1.f / l1;
    float* ob0 = op + (size_t)split * MQ * HID + (qrow0 + wr) * HID + hoff;
    float* ob1 = op + (size_t)split * MQ * HID + (qrow0 + wr + 8) * HID + hoff;
    #pragma unroll
    for (int j2 = 0; j2 < 16; j2++) {
        *(float2*)(ob0 + j2 * 8 + 2 * tg) = make_float2(Oacc[j2][0] * inv0, Oacc[j2][1] * inv0);
        *(float2*)(ob1 + j2 * 8 + 2 * tg) = make_float2(Oacc[j2][2] * inv1, Oacc[j2][3] * inv1);
    }
    if (tg == 0) {
        int qloc = blockIdx.x * 128;
        long base = ((long)split * BB * NH + bh) * NQT;
        pm[base + qloc + wr]     = m0;
        pl[base + qloc + wr]     = l0;
        pm[base + qloc + wr + 8] = m1;
        pl[base + qloc + wr + 8] = l1;
    }
}

// ---------------- split-combine: O = (w0*O0 + w1*O1)/(w0+w1) ----------------
__global__ void combine_o(const float* __restrict__ op, const float* __restrict__ pm,
                          const float* __restrict__ pl, float* __restrict__ go)
{
    long idx = (long)blockIdx.x * blockDim.x + threadIdx.x;
    if (idx >= (long)MQ * HID / 4) return;
    int row = (int)(idx / (HID / 4));
    int col = (int)(idx % (HID / 4)) * 4;
    int h = col >> 7;
    int b = row / NQT, qr = row - b * NQT;
    long mi = ((long)b * NH + h) * NQT + qr;
    float m0 = pm[mi], m1 = pm[(long)BB * NH * NQT + mi];
    float l0 = pl[mi], l1 = pl[(long)BB * NH * NQT + mi];
    float M = fmaxf(m0, m1);
    float w0 = __expf(m0 - M) * l0, w1 = __expf(m1 - M) * l1;
    float inv = 1.f / (w0 + w1);
    w0 *= inv; w1 *= inv;
    float4 a = *(const float4*)(op + (size_t)row * HID + col);
    float4 c = *(const float4*)(op + (size_t)MQ * HID + (size_t)row * HID + col);
    *(float4*)(go + (size_t)row * HID + col) =
        make_float4(w0 * a.x + w1 * c.x, w0 * a.y + w1 * c.y,
                    w0 * a.z + w1 * c.z, w0 * a.w + w1 * c.w);
}

// ---------------- fp16 mma GEMM, templated M-tile (MI*64 rows x 128 cols) ---
#define TW 20
#define BTILE_W (128 * TW)

template<int MI>
__global__ void __launch_bounds__(256)
tgemm(const float* __restrict__ A, const float* __restrict__ Bt,
      const float* __restrict__ bias, float* __restrict__ C,
      int M, int N, int K, int lda, int ldb, int ldc, int act)
{
    extern __shared__ __align__(16) uint32_t smem[];
    const int ATILE_W = MI * 64 * TW;

    int m0 = blockIdx.y * (MI * 64), n0 = blockIdx.x << 7;
    int tid = threadIdx.x, wid = tid >> 5, lane = tid & 31;
    int wm = wid >> 1, wn = wid & 1;
    int g = lane >> 2, tg = lane & 3;

    int lr = tid >> 1, wc = (tid & 1) << 3;
    bool aActive = (MI == 2) || (lr < 64);
    const float* aptr = A + (long)(m0 + (aActive ? lr : 0)) * lda + (wc << 1);
    const float* bptr = Bt + (long)(n0 + lr) * ldb + (wc << 1);
    int sidx = lr * TW + wc;

    uint32_t* Abuf[2] = { smem,           smem + ATILE_W + BTILE_W };
    uint32_t* Bbuf[2] = { smem + ATILE_W, smem + 2 * ATILE_W + BTILE_W };

    float acc[MI][8][4];
    #pragma unroll
    for (int i = 0; i < MI; i++)
        #pragma unroll
        for (int j = 0; j < 8; j++)
            #pragma unroll
            for (int c = 0; c < 4; c++) acc[i][j][c] = 0.f;

    int aRow = wm * (MI * 16) + g;
    int bRow = wn * 64 + g;

    float4 av[4], bv[4];
    #pragma unroll
    for (int i = 0; i < 4; i++) {
        if (aActive) av[i] = *(const float4*)(aptr + i * 4);
        bv[i] = *(const float4*)(bptr + i * 4);
    }
    {
        uint4 u;
        if (aActive) {
            u.x = f2h2(av[0].x, av[0].y); u.y = f2h2(av[0].z, av[0].w);
            u.z = f2h2(av[1].x, av[1].y); u.w = f2h2(av[1].z, av[1].w);
            *(uint4*)(Abuf[0] + sidx) = u;
            u.x = f2h2(av[2].x, av[2].y); u.y = f2h2(av[2].z, av[2].w);
            u.z = f2h2(av[3].x, av[3].y); u.w = f2h2(av[3].z, av[3].w);
            *(uint4*)(Abuf[0] + sidx + 4) = u;
        }
        u.x = f2h2(bv[0].x, bv[0].y); u.y = f2h2(bv[0].z, bv[0].w);
        u.z = f2h2(bv[1].x, bv[1].y); u.w = f2h2(bv[1].z, bv[1].w);
        *(uint4*)(Bbuf[0] + sidx) = u;
        u.x = f2h2(bv[2].x, bv[2].y); u.y = f2h2(bv[2].z, bv[2].w);
        u.z = f2h2(bv[3].x, bv[3].y); u.w = f2h2(bv[3].z, bv[3].w);
        *(uint4*)(Bbuf[0] + sidx + 4) = u;
    }
    __syncthreads();

    int nkt = K >> 5;
    for (int kt = 0; kt < nkt; kt++) {
        int buf = kt & 1;
        bool more = (kt + 1) < nkt;
        if (more) {
            int k0 = (kt + 1) << 5;
            #pragma unroll
            for (int i = 0; i < 4; i++) {
                if (aActive) av[i] = *(const float4*)(aptr + k0 + i * 4);
                bv[i] = *(const float4*)(bptr + k0 + i * 4);
            }
        }
        const uint32_t* Au = Abuf[buf];
        const uint32_t* Bu = Bbuf[buf];
        #pragma unroll
        for (int kk2 = 0; kk2 < 16; kk2 += 8) {
            uint32_t af[MI][4], bf[8][2];
            #pragma unroll
            for (int i = 0; i < MI; i++) {
                int base = (aRow + i * 16) * TW + kk2 + tg;
                af[i][0] = Au[base];
                af[i][1] = Au[base + 8 * TW];
                af[i][2] = Au[base + 4];
                af[i][3] = Au[base + 8 * TW + 4];
            }
            #pragma unroll
            for (int j = 0; j < 8; j++) {
                int base = (bRow + j * 8) * TW + kk2 + tg;
                bf[j][0] = Bu[base];
                bf[j][1] = Bu[base + 4];
            }
            #pragma unroll
            for (int i = 0; i < MI; i++)
                #pragma unroll
                for (int j = 0; j < 8; j++)
                    mma_f16(acc[i][j], af[i], bf[j]);
        }
        if (more) {
            uint32_t* Ad = Abuf[buf ^ 1];
            uint32_t* Bd = Bbuf[buf ^ 1];
            uint4 u;
            if (aActive) {
                u.x = f2h2(av[0].x, av[0].y); u.y = f2h2(av[0].z, av[0].w);
                u.z = f2h2(av[1].x, av[1].y); u.w = f2h2(av[1].z, av[1].w);
                *(uint4*)(Ad + sidx) = u;
                u.x = f2h2(av[2].x, av[2].y); u.y = f2h2(av[2].z, av[2].w);
                u.z = f2h2(av[3].x, av[3].y); u.w = f2h2(av[3].z, av[3].w);
                *(uint4*)(Ad + sidx + 4) = u;
            }
            u.x = f2h2(bv[0].x, bv[0].y); u.y = f2h2(bv[0].z, bv[0].w);
            u.z = f2h2(bv[1].x, bv[1].y); u.w = f2h2(bv[1].z, bv[1].w);
            *(uint4*)(Bd + sidx) = u;
            u.x = f2h2(bv[2].x, bv[2].y); u.y = f2h2(bv[2].z, bv[2].w);
            u.z = f2h2(bv[3].x, bv[3].y); u.w = f2h2(bv[3].z, bv[3].w);
            *(uint4*)(Bd + sidx + 4) = u;
        }
        __syncthreads();
    }

    #pragma unroll
    for (int i = 0; i < MI; i++) {
        int row0 = m0 + wm * (MI * 16) + i * 16 + g;
        #pragma unroll
        for (int j = 0; j < 8; j++) {
            int col = n0 + wn * 64 + j * 8 + 2 * tg;
            float b0 = 0.f, b1 = 0.f;
            if (bias) { b0 = bias[col]; b1 = bias[col + 1]; }
            #pragma unroll
            for (int half = 0; half < 2; half++) {
                float v0 = acc[i][j][half * 2]     + b0;
                float v1 = acc[i][j][half * 2 + 1] + b1;
                if (act) {
                    float x3 = v0 * v0 * v0;
                    v0 = 0.5f * v0 * (1.f + tanhf(0.7978845608028654f * (v0 + 0.044715f * x3)));
                    x3 = v1 * v1 * v1;
                    v1 = 0.5f * v1 * (1.f + tanhf(0.7978845608028654f * (v1 + 0.044715f * x3)));
                }
                *(float2*)(C + (long)(row0 + half * 8) * ldc + col) = make_float2(v0, v1);
            }
        }
    }
}

#define GEMM_SMEM1 ((64 * TW + BTILE_W) * 2 * 4)    // 30720
#define GEMM_SMEM2 ((128 * TW + BTILE_W) * 2 * 4)   // 40960

// ---------------- batched weight transpose (one launch for all 9) ----------
struct TransDesc { const float* src; float* dst; int R; int C; int bstart; };
struct TransArgs { TransDesc d[9]; };

__global__ void transpose_all(TransArgs a)
{
    __shared__ float t[32][33];
    int bid = blockIdx.x;
    int i = 0;
    #pragma unroll
    for (int j = 1; j < 9; j++)
        if (bid >= a.d[j].bstart) i = j;
    const float* src = a.d[i].src;
    float* dst = a.d[i].dst;
    int R = a.d[i].R, Cc = a.d[i].C;
    int bt = bid - a.d[i].bstart;
    int tpr = Cc >> 5;
    int c0 = (bt % tpr) << 5, r0 = (bt / tpr) << 5;
    int x = threadIdx.x, y = threadIdx.y;
    #pragma unroll
    for (int k = 0; k < 32; k += 8)
        t[y + k][x] = src[(long)(r0 + y + k) * Cc + c0 + x];
    __syncthreads();
    #pragma unroll
    for (int k = 0; k < 32; k += 8)
        dst[(long)(c0 + y + k) * R + r0 + x] = t[x][y + k];
}

// ---------------- V transpose: vt[z][d][kv] = v[b*NKT+kv][h*HD+d] ----------
__global__ void vtrans(const float* __restrict__ v, float* __restrict__ vt)
{
    __shared__ float t[32][33];
    int z = blockIdx.z;
    int b = z >> 2, h = z & 3;
    int kv0 = blockIdx.x * 32, d0 = blockIdx.y * 32;
    int x = threadIdx.x, y = threadIdx.y;
    const float* src = v + ((long)b * NKT + kv0) * HID + h * HD + d0;
    #pragma unroll
    for (int i = 0; i < 32; i += 8)
        t[y + i][x] = src[(long)(y + i) * HID + x];
    __syncthreads();
    float* dst = vt + ((size_t)z * HD + d0) * NKT + kv0;
    #pragma unroll
    for (int i = 0; i < 32; i += 8)
        dst[(long)(y + i) * NKT + x] = t[x][y + i];
}

// ---------------- kv input mapping ----------------
__global__ void kvmap(const float* __restrict__ x, const float* __restrict__ Wm,
                      const float* __restrict__ bm, float* __restrict__ kv)
{
    int gg = blockIdx.x * blockDim.x + threadIdx.x;
    if (gg >= MKV * 256) return;
    int m = gg >> 8, e4 = (gg & 255) << 2;
    float4 acc = *(const float4*)(bm + e4);
    #pragma unroll
    for (int c = 0; c < 4; c++) {
        float xv = x[m * 4 + c];
        float4 w = *(const float4*)(Wm + c * EMB + e4);
        acc.x += xv * w.x; acc.y += xv * w.y; acc.z += xv * w.z; acc.w += xv * w.w;
    }
    *(float4*)(kv + (long)m * EMB + e4) = acc;
}

// ---------------- 3D RoPE (q and k in one launch) ----------------
__device__ __forceinline__ void rope_pair(float* base, int f, float t, float py, float px)
{
    int sel = (f < 22) ? 0 : ((f < 43) ? 1 : 2);
    float pos = (sel == 0) ? t : ((sel == 1) ? py : px);
    float ang = pos * exp2f(-(float)f * 0.2076205059304601f);
    float c = cosf(ang), s = sinf(ang);
    float x0 = base[f], x1 = base[f + 64];
    base[f]      = x0 * c - x1 * s;
    base[f + 64] = x1 * c + x0 * s;
}

__global__ void rope_all(float* __restrict__ q, float* __restrict__ k)
{
    const long NQE = (long)MQ * NH * 64;
    const long NKE = (long)MKV * NH * 64;
    long idx = (long)blockIdx.x * blockDim.x + threadIdx.x;
    if (idx < NQE) {
        int f = (int)(idx & 63);
        int head = (int)((idx >> 6) & 3);
        long row = idx >> 8;
        int n = (int)(row % NQT);
        int t = n / NQc, g = n % NQc;
        rope_pair(q + row * HID + head * HD, f, (float)t, (float)(g / 14), (float)(g % 14));
    } else if (idx < NQE + NKE) {
        idx -= NQE;
        int f = (int)(idx & 63);
        int head = (int)((idx >> 6) & 3);
        long row = idx >> 8;
        int n = (int)(row % NKT);
        int t = n / 64, g = n % 64;
        rope_pair(k + row * HID + head * HD, f, (float)t, (float)(g / 8), (float)(g % 8));
    }
}

// ---------------- residual add + LayerNorm ----------------
__global__ void add_ln(const float* __restrict__ X, const float* __restrict__ Y,
                       const float* __restrict__ g, const float* __restrict__ b,
                       float* __restrict__ out)
{
    long row = blockIdx.x;
    const float* x = X + row * HID;
    const float* y = Y + row * HID;
    int tid = threadIdx.x;
    float v[4]; float s = 0.f, s2 = 0.f;
    #pragma unroll
    for (int i = 0; i < 4; i++) {
        v[i] = x[tid + 128 * i] + y[tid + 128 * i];
        s += v[i]; s2 += v[i] * v[i];
    }
    __shared__ float rs[4], rs2[4];
    #pragma unroll
    for (int o = 16; o > 0; o >>= 1) {
        s  += __shfl_xor_sync(~0u, s, o);
        s2 += __shfl_xor_sync(~0u, s2, o);
    }
    if ((tid & 31) == 0) { rs[tid >> 5] = s; rs2[tid >> 5] = s2; }
    __syncthreads();
    s  = rs[0] + rs[1] + rs[2] + rs[3];
    s2 = rs2[0] + rs2[1] + rs2[2] + rs2[3];
    float mean = s * (1.f / HID);
    float var  = s2 * (1.f / HID) - mean * mean;
    float inv  = rsqrtf(var + 1e-5f);
    float* o = out + row * HID;
    #pragma unroll
    for (int i = 0; i < 4; i++) {
        int c = tid + 128 * i;
        o[c] = (v[i] - mean) * inv * g[c] + b[c];
    }
}

// ---------------- host orchestration ----------------
static inline dim3 G1(int M, int N) { return dim3(N >> 7, M / 64); }   // MI=1
static inline dim3 G2(int M, int N) { return dim3(N >> 7, M >> 7); }   // MI=2

extern "C" void kernel_launch(void* const* d_in, const int* in_sizes, int n_in,
                              void* d_out, int out_size)
{
    (void)in_sizes; (void)n_in; (void)out_size;
    const float* x_in  = (const float*)d_in[0];
    const float* slow  = (const float*)d_in[1];
    const float* Wq_in = (const float*)d_in[3];
    const float* bq_in = (const float*)d_in[4];
    const float* Wm  = (const float*)d_in[5];
    const float* bm  = (const float*)d_in[6];
    const float* Wq  = (const float*)d_in[7];
    const float* bq  = (const float*)d_in[8];
    const float* Wk  = (const float*)d_in[9];
    const float* bk  = (const float*)d_in[10];
    const float* Wv  = (const float*)d_in[11];
    const float* bv  = (const float*)d_in[12];
    const float* Wo  = (const float*)d_in[13];
    const float* bo  = (const float*)d_in[14];
    const float* g1  = (const float*)d_in[15];
    const float* be1 = (const float*)d_in[16];
    const float* W1  = (const float*)d_in[17];
    const float* b1  = (const float*)d_in[18];
    const float* W2  = (const float*)d_in[19];
    const float* b2  = (const float*)d_in[20];
    const float* g2  = (const float*)d_in[21];
    const float* be2 = (const float*)d_in[22];
    const float* M1  = (const float*)d_in[23];
    const float* bm1 = (const float*)d_in[24];
    const float* M2  = (const float*)d_in[25];
    const float* bm2 = (const float*)d_in[26];
    float* out = (float*)d_out;

    float *qin, *kv, *q, *k, *v, *o, *h, *ff, *h2, *vt, *op, *pm, *pl;
    float *wqinT, *wqT, *wkT, *wvT, *woT, *w1T, *w2T, *m1T, *m2T;
    cudaGetSymbolAddress((void**)&qin, g_qin);
    cudaGetSymbolAddress((void**)&kv,  g_kv);
    cudaGetSymbolAddress((void**)&q,   g_q);
    cudaGetSymbolAddress((void**)&k,   g_k);
    cudaGetSymbolAddress((void**)&v,   g_v);
    cudaGetSymbolAddress((void**)&o,   g_o);
    cudaGetSymbolAddress((void**)&h,   g_h);
    cudaGetSymbolAddress((void**)&ff,  g_ff);
    cudaGetSymbolAddress((void**)&h2,  g_h2);
    cudaGetSymbolAddress((void**)&vt,  g_vt);
    cudaGetSymbolAddress((void**)&op,  g_op);
    cudaGetSymbolAddress((void**)&pm,  g_pm);
    cudaGetSymbolAddress((void**)&pl,  g_pl);
    cudaGetSymbolAddress((void**)&wqinT, g_wqinT);
    cudaGetSymbolAddress((void**)&wqT,   g_wqT);
    cudaGetSymbolAddress((void**)&wkT,   g_wkT);
    cudaGetSymbolAddress((void**)&wvT,   g_wvT);
    cudaGetSymbolAddress((void**)&woT,   g_woT);
    cudaGetSymbolAddress((void**)&w1T,   g_w1T);
    cudaGetSymbolAddress((void**)&w2T,   g_w2T);
    cudaGetSymbolAddress((void**)&m1T,   g_m1T);
    cudaGetSymbolAddress((void**)&m2T,   g_m2T);

    static int attr_set = 0;
    if (!attr_set) {
        cudaFuncSetAttribute(flash_attn, cudaFuncAttributeMaxDynamicSharedMemorySize, FLASH_SMEM);
        attr_set = 1;
    }

    // batched weight transposes: (R, C) of source [R,C] -> dst [C,R]
    TransArgs ta;
    ta.d[0] = { Wq_in, wqinT,  896,  512,    0 };   // 16x28 = 448
    ta.d[1] = { Wq,    wqT,    512,  512,  448 };   // 256
    ta.d[2] = { Wk,    wkT,   1024,  512,  704 };   // 512
    ta.d[3] = { Wv,    wvT,   1024,  512, 1216 };   // 512
    ta.d[4] = { Wo,    woT,    512,  512, 1728 };   // 256
    ta.d[5] = { W1,    w1T,    512, 1024, 1984 };   // 512
    ta.d[6] = { W2,    w2T,   1024,  512, 2496 };   // 512
    ta.d[7] = { M1,    m1T,    512, 1024, 3008 };   // 512
    ta.d[8] = { M2,    m2T,   1024,  896, 3520 };   // 896 -> total 4416

    dim3 tb(32, 8);
    transpose_all<<<4416, tb>>>(ta);
    kvmap<<<(MKV * 256 + 255) / 256, 256>>>(x_in, Wm, bm, kv);

    // q_in = slow @ Wq_in + bq_in
    tgemm<1><<<G1(MQ, HID), 256, GEMM_SMEM1>>>(slow, wqinT, bq_in, qin,
        MQ, HID, DQ, DQ, DQ, HID, 0);
    // projections
    tgemm<1><<<G1(MQ, HID), 256, GEMM_SMEM1>>>(qin, wqT, bq, q,
        MQ, HID, HID, HID, HID, HID, 0);
    tgemm<1><<<G1(MKV, HID), 256, GEMM_SMEM1>>>(kv, wkT, bk, k,
        MKV, HID, EMB, EMB, EMB, HID, 0);
    tgemm<1><<<G1(MKV, HID), 256, GEMM_SMEM1>>>(kv, wvT, bv, v,
        MKV, HID, EMB, EMB, EMB, HID, 0);
    // RoPE (q + k fused)
    {
        long tot = (long)MQ * NH * 64 + (long)MKV * NH * 64;
        rope_all<<<(int)((tot + 255) / 256), 256>>>(q, k);
    }
    // V transpose per (b,h)
    vtrans<<<dim3(NKT/32, HD/32, BB * NH), tb>>>(v, vt);
    // split-KV flash attention + combine
    flash_attn<<<dim3(NQT / 128, BB * NH, NSPLIT), 256, FLASH_SMEM>>>(q, k, vt, op, pm, pl);
    combine_o<<<(int)(((long)MQ * HID / 4 + 255) / 256), 256>>>(op, pm, pl, o);
    // o_proj (reuse q)
    tgemm<1><<<G1(MQ, HID), 256, GEMM_SMEM1>>>(o, woT, bo, q,
        MQ, HID, HID, HID, HID, HID, 0);
    add_ln<<<MQ, 128>>>(qin, q, g1, be1, h);
    tgemm<2><<<G2(MQ, FFD), 256, GEMM_SMEM2>>>(h, w1T, b1, ff,
        MQ, FFD, HID, HID, HID, FFD, 1);
    tgemm<1><<<G1(MQ, HID), 256, GEMM_SMEM1>>>(ff, w2T, b2, o,
        MQ, HID, FFD, FFD, FFD, HID, 0);
    add_ln<<<MQ, 128>>>(h, o, g2, be2, h2);
    tgemm<2><<<G2(MQ, FFD), 256, GEMM_SMEM2>>>(h2, m1T, bm1, ff,
        MQ, FFD, HID, HID, HID, FFD, 1);
    tgemm<1><<<G1(MQ, OUTD), 256, GEMM_SMEM1>>>(ff, m2T, bm2, out,
        MQ, OUTD, FFD, FFD, FFD, OUTD, 0);
}

// round 11
// speedup vs baseline: 1.2555x; 1.2555x over previous
#include <cuda_runtime.h>
#include <cuda_fp16.h>
#include <math.h>
#include <stdint.h>

// ---------------- problem dims ----------------
#define BB   2
#define TQc  32
#define NQc  196
#define DQ   896
#define NQT  6272
#define MQ   12544
#define NKT  2048
#define MKV  4096
#define CIN  4
#define EMB  1024
#define HID  512
#define NH   4
#define HD   128
#define FFD  1024
#define OUTD 896

// ---------------- scratch ----------------
__device__ float g_qin[(size_t)MQ * HID];
__device__ float g_kv [(size_t)MKV * EMB];
__device__ float g_q  [(size_t)MQ * HID];
__device__ float g_k  [(size_t)MKV * HID];
__device__ float g_v  [(size_t)MKV * HID];
__device__ float g_o  [(size_t)MQ * HID];
__device__ float g_h  [(size_t)MQ * HID];
__device__ float g_ff [(size_t)MQ * FFD];
__device__ float g_h2 [(size_t)MQ * HID];
__device__ float g_vt [(size_t)BB * NH * HD * NKT];
// transposed weights [N,K]
__device__ float g_wqinT[512 * 896];
__device__ float g_wqT  [512 * 512];
__device__ float g_wkT  [512 * 1024];
__device__ float g_wvT  [512 * 1024];
__device__ float g_woT  [512 * 512];
__device__ float g_w1T  [1024 * 512];
__device__ float g_w2T  [512 * 1024];
__device__ float g_m1T  [1024 * 512];
__device__ float g_m2T  [896 * 1024];

// ---------------- fp16 helpers ----------------
__device__ __forceinline__ uint32_t f2h2(float a, float b)
{
    __half2 h = __float22half2_rn(make_float2(a, b));
    return *(uint32_t*)&h;
}

__device__ __forceinline__ void mma_f16(float* d, const uint32_t* a, const uint32_t* b)
{
    asm volatile(
        "mma.sync.aligned.m16n8k16.row.col.f32.f16.f16.f32 "
        "{%0,%1,%2,%3}, {%4,%5,%6,%7}, {%8,%9}, {%0,%1,%2,%3};\n"
        : "+f"(d[0]), "+f"(d[1]), "+f"(d[2]), "+f"(d[3])
        : "r"(a[0]), "r"(a[1]), "r"(a[2]), "r"(a[3]), "r"(b[0]), "r"(b[1]));
}

__device__ __forceinline__ void ldsm_x4(uint32_t& r0, uint32_t& r1, uint32_t& r2,
                                        uint32_t& r3, uint32_t addr)
{
    asm volatile("ldmatrix.sync.aligned.m8n8.x4.shared.b16 {%0,%1,%2,%3}, [%4];"
        : "=r"(r0), "=r"(r1), "=r"(r2), "=r"(r3) : "r"(addr));
}

// A-operand lane mapping for ldmatrix x4 over a 16row x 16half tile:
//   rowOff = ((lane>>3)&1)*8 + (lane&7), wordOff = (lane>>4)*4
// B-operand (two adjacent 8-col j-tiles x 16half):
//   rowOff = (lane>>4)*8 + (lane&7),     wordOff = ((lane>>3)&1)*4

// =================================================================
// Fused flash attention, fp16 mma + ldmatrix.
// Grid (NQT/128, BB*NH), 256 thr (8 warps x 16 q-rows).
// =================================================================
#define FQ_W 68
#define FV_W 36
#define FLASH_WORDS (128*FQ_W + 64*FQ_W + 128*FV_W + 128*FV_W)
#define FLASH_SMEM (FLASH_WORDS * 4)   // 89088 B

__global__ void __launch_bounds__(256)
flash_attn(const float* __restrict__ gq, const float* __restrict__ gk,
           const float* __restrict__ gvt, float* __restrict__ go)
{
    extern __shared__ __align__(16) uint32_t sh[];
    uint32_t* Qs = sh;
    uint32_t* Ks = sh + 128 * FQ_W;
    uint32_t* Vs = Ks + 64 * FQ_W;
    uint32_t* Ps = Vs + 128 * FV_W;
    uint32_t sb = (uint32_t)__cvta_generic_to_shared(sh);
    uint32_t qbase = sb;
    uint32_t kbase = sb + 128 * FQ_W * 4;
    uint32_t vbase = kbase + 64 * FQ_W * 4;
    uint32_t pbase = vbase + 128 * FV_W * 4;

    int b = blockIdx.y >> 2, h = blockIdx.y & 3;
    int hoff = h * HD;
    long qrow0 = (long)b * NQT + (long)blockIdx.x * 128;
    long kvrow0 = (long)b * NKT;
    const float* vtbase = gvt + (size_t)blockIdx.y * HD * NKT;

    int tid = threadIdx.x, w = tid >> 5, lane = tid & 31;
    int g = lane >> 2, tg = lane & 3;
    int wr = w * 16 + g;

    int aRowOff = ((lane >> 3) & 1) * 8 + (lane & 7);
    int aWordOff = (lane >> 4) * 4;
    int bRowOff = (lane >> 4) * 8 + (lane & 7);
    int bWordOff = ((lane >> 3) & 1) * 4;

    // ---- stage Q tile (128x128) as fp16 ----
    {
        int row = tid >> 1, fseg = (tid & 1) << 6;
        const float* src = gq + (qrow0 + row) * HID + hoff + fseg;
        uint32_t* dst = Qs + row * FQ_W + (fseg >> 1);
        #pragma unroll
        for (int i = 0; i < 8; i++) {
            float4 v0 = *(const float4*)(src + i * 8);
            float4 v1 = *(const float4*)(src + i * 8 + 4);
            uint4 u;
            u.x = f2h2(v0.x, v0.y); u.y = f2h2(v0.z, v0.w);
            u.z = f2h2(v1.x, v1.y); u.w = f2h2(v1.z, v1.w);
            *(uint4*)(dst + i * 4) = u;
        }
    }

    float Oacc[16][4];
    #pragma unroll
    for (int j = 0; j < 16; j++)
        #pragma unroll
        for (int c = 0; c < 4; c++) Oacc[j][c] = 0.f;
    float m0 = -1e30f, m1 = -1e30f, l0 = 0.f, l1 = 0.f;

    const float scale = 0.08838834764831845f;
    int kvr = tid >> 2, kfs = (tid & 3) << 5;
    int vr = tid >> 1, vfs = (tid & 1) << 5;

    for (int jt = 0; jt < NKT / 64; jt++) {
        __syncthreads();
        {
            const float* ksrc = gk + (kvrow0 + jt * 64 + kvr) * HID + hoff + kfs;
            uint32_t* kd = Ks + kvr * FQ_W + (kfs >> 1);
            #pragma unroll
            for (int i = 0; i < 4; i++) {
                float4 v0 = *(const float4*)(ksrc + i * 8);
                float4 v1 = *(const float4*)(ksrc + i * 8 + 4);
                uint4 u;
                u.x = f2h2(v0.x, v0.y); u.y = f2h2(v0.z, v0.w);
                u.z = f2h2(v1.x, v1.y); u.w = f2h2(v1.z, v1.w);
                *(uint4*)(kd + i * 4) = u;
            }
            const float* vsrc = vtbase + (size_t)vr * NKT + jt * 64 + vfs;
            uint32_t* vd = Vs + vr * FV_W + (vfs >> 1);
            #pragma unroll
            for (int i = 0; i < 4; i++) {
                float4 v0 = *(const float4*)(vsrc + i * 8);
                float4 v1 = *(const float4*)(vsrc + i * 8 + 4);
                uint4 u;
                u.x = f2h2(v0.x, v0.y); u.y = f2h2(v0.z, v0.w);
                u.z = f2h2(v1.x, v1.y); u.w = f2h2(v1.z, v1.w);
                *(uint4*)(vd + i * 4) = u;
            }
        }
        __syncthreads();

        // ---- S = Q.K^T (ldmatrix) ----
        float S[8][4];
        #pragma unroll
        for (int j = 0; j < 8; j++)
            #pragma unroll
            for (int c = 0; c < 4; c++) S[j][c] = 0.f;
        {
            uint32_t qa = qbase + ((w * 16 + aRowOff) * FQ_W + aWordOff) * 4;
            uint32_t kb = kbase + ((bRowOff) * FQ_W + bWordOff) * 4;
            #pragma unroll
            for (int kk2 = 0; kk2 < 64; kk2 += 8) {
                uint32_t af[4];
                ldsm_x4(af[0], af[1], af[2], af[3], qa + kk2 * 4);
                #pragma unroll
                for (int jj = 0; jj < 4; jj++) {
                    uint32_t bf4[4];
                    ldsm_x4(bf4[0], bf4[1], bf4[2], bf4[3],
                            kb + (jj * 16 * FQ_W + kk2) * 4);
                    mma_f16(S[2 * jj],     af, bf4);
                    mma_f16(S[2 * jj + 1], af, bf4 + 2);
                }
            }
        }

        // ---- online softmax ----
        float mx0 = -1e30f, mx1 = -1e30f;
        #pragma unroll
        for (int j = 0; j < 8; j++) {
            #pragma unroll
            for (int c = 0; c < 4; c++) S[j][c] *= scale;
            mx0 = fmaxf(mx0, fmaxf(S[j][0], S[j][1]));
            mx1 = fmaxf(mx1, fmaxf(S[j][2], S[j][3]));
        }
        mx0 = fmaxf(mx0, __shfl_xor_sync(~0u, mx0, 1));
        mx0 = fmaxf(mx0, __shfl_xor_sync(~0u, mx0, 2));
        mx1 = fmaxf(mx1, __shfl_xor_sync(~0u, mx1, 1));
        mx1 = fmaxf(mx1, __shfl_xor_sync(~0u, mx1, 2));
        float mn0 = fmaxf(m0, mx0), mn1 = fmaxf(m1, mx1);
        float al0 = __expf(m0 - mn0), al1 = __expf(m1 - mn1);
        m0 = mn0; m1 = mn1;
        float sum0 = 0.f, sum1 = 0.f;
        uint32_t* prow0 = Ps + wr * FV_W;
        uint32_t* prow1 = Ps + (wr + 8) * FV_W;
        #pragma unroll
        for (int j = 0; j < 8; j++) {
            float p0 = __expf(S[j][0] - mn0);
            float p1 = __expf(S[j][1] - mn0);
            float p2 = __expf(S[j][2] - mn1);
            float p3 = __expf(S[j][3] - mn1);
            sum0 += p0 + p1; sum1 += p2 + p3;
            prow0[4 * j + tg] = f2h2(p0, p1);
            prow1[4 * j + tg] = f2h2(p2, p3);
        }
        sum0 += __shfl_xor_sync(~0u, sum0, 1);
        sum0 += __shfl_xor_sync(~0u, sum0, 2);
        sum1 += __shfl_xor_sync(~0u, sum1, 1);
        sum1 += __shfl_xor_sync(~0u, sum1, 2);
        l0 = l0 * al0 + sum0;
        l1 = l1 * al1 + sum1;
        #pragma unroll
        for (int j = 0; j < 16; j++) {
            Oacc[j][0] *= al0; Oacc[j][1] *= al0;
            Oacc[j][2] *= al1; Oacc[j][3] *= al1;
        }
        __syncwarp();

        // ---- O += P.V (ldmatrix) ----
        {
            uint32_t pa = pbase + ((w * 16 + aRowOff) * FV_W + aWordOff) * 4;
            uint32_t vb = vbase + ((bRowOff) * FV_W + bWordOff) * 4;
            #pragma unroll
            for (int kk2 = 0; kk2 < 32; kk2 += 8) {
                uint32_t af[4];
                ldsm_x4(af[0], af[1], af[2], af[3], pa + kk2 * 4);
                #pragma unroll
                for (int jj = 0; jj < 8; jj++) {
                    uint32_t bf4[4];
                    ldsm_x4(bf4[0], bf4[1], bf4[2], bf4[3],
                            vb + (jj * 16 * FV_W + kk2) * 4);
                    mma_f16(Oacc[2 * jj],     af, bf4);
                    mma_f16(Oacc[2 * jj + 1], af, bf4 + 2);
                }
            }
        }
        __syncwarp();
    }

    float inv0 = 1.f / l0, inv1 = 1.f / l1;
    float* ob0 = go + (qrow0 + wr) * HID + hoff;
    float* ob1 = go + (qrow0 + wr + 8) * HID + hoff;
    #pragma unroll
    for (int j2 = 0; j2 < 16; j2++) {
        *(float2*)(ob0 + j2 * 8 + 2 * tg) = make_float2(Oacc[j2][0] * inv0, Oacc[j2][1] * inv0);
        *(float2*)(ob1 + j2 * 8 + 2 * tg) = make_float2(Oacc[j2][2] * inv1, Oacc[j2][3] * inv1);
    }
}

// ---------------- fp16 mma GEMM (128x128 tile) + ldmatrix ----------------
#define TW 20
#define TILE_W (128 * TW)
#define GEMM_SMEM (4 * TILE_W * 4)   // 40960 B

__global__ void __launch_bounds__(256)
tgemm(const float* __restrict__ A, const float* __restrict__ Bt,
      const float* __restrict__ bias, float* __restrict__ C,
      int M, int N, int K, int lda, int ldb, int ldc, int act)
{
    extern __shared__ __align__(16) uint32_t smem[];
    uint32_t sb = (uint32_t)__cvta_generic_to_shared(smem);

    int m0 = blockIdx.y << 7, n0 = blockIdx.x << 7;
    int tid = threadIdx.x, wid = tid >> 5, lane = tid & 31;
    int wm = wid >> 1, wn = wid & 1;
    int g = lane >> 2, tg = lane & 3;

    int lr = tid >> 1, wc = (tid & 1) << 3;
    const float* aptr = A + (long)(m0 + lr) * lda + (wc << 1);
    const float* bptr = Bt + (long)(n0 + lr) * ldb + (wc << 1);
    int sidx = lr * TW + wc;

    uint32_t* Abuf[2] = { smem,          smem + 2 * TILE_W };
    uint32_t* Bbuf[2] = { smem + TILE_W, smem + 3 * TILE_W };
    uint32_t abase[2] = { sb,                sb + 2 * TILE_W * 4 };
    uint32_t bbase[2] = { sb + TILE_W * 4,   sb + 3 * TILE_W * 4 };

    int aRowOff = ((lane >> 3) & 1) * 8 + (lane & 7);
    int aWordOff = (lane >> 4) * 4;
    int bRowOff = (lane >> 4) * 8 + (lane & 7);
    int bWordOff = ((lane >> 3) & 1) * 4;

    float acc[2][8][4];
    #pragma unroll
    for (int i = 0; i < 2; i++)
        #pragma unroll
        for (int j = 0; j < 8; j++)
            #pragma unroll
            for (int c = 0; c < 4; c++) acc[i][j][c] = 0.f;

    float4 av[4], bv[4];
    #pragma unroll
    for (int i = 0; i < 4; i++) {
        av[i] = *(const float4*)(aptr + i * 4);
        bv[i] = *(const float4*)(bptr + i * 4);
    }
    {
        uint4 u;
        u.x = f2h2(av[0].x, av[0].y); u.y = f2h2(av[0].z, av[0].w);
        u.z = f2h2(av[1].x, av[1].y); u.w = f2h2(av[1].z, av[1].w);
        *(uint4*)(Abuf[0] + sidx) = u;
        u.x = f2h2(av[2].x, av[2].y); u.y = f2h2(av[2].z, av[2].w);
        u.z = f2h2(av[3].x, av[3].y); u.w = f2h2(av[3].z, av[3].w);
        *(uint4*)(Abuf[0] + sidx + 4) = u;
        u.x = f2h2(bv[0].x, bv[0].y); u.y = f2h2(bv[0].z, bv[0].w);
        u.z = f2h2(bv[1].x, bv[1].y); u.w = f2h2(bv[1].z, bv[1].w);
        *(uint4*)(Bbuf[0] + sidx) = u;
        u.x = f2h2(bv[2].x, bv[2].y); u.y = f2h2(bv[2].z, bv[2].w);
        u.z = f2h2(bv[3].x, bv[3].y); u.w = f2h2(bv[3].z, bv[3].w);
        *(uint4*)(Bbuf[0] + sidx + 4) = u;
    }
    __syncthreads();

    int nkt = K >> 5;
    for (int kt = 0; kt < nkt; kt++) {
        int buf = kt & 1;
        bool more = (kt + 1) < nkt;
        if (more) {
            int k0 = (kt + 1) << 5;
            #pragma unroll
            for (int i = 0; i < 4; i++) {
                av[i] = *(const float4*)(aptr + k0 + i * 4);
                bv[i] = *(const float4*)(bptr + k0 + i * 4);
            }
        }
        uint32_t au = abase[buf] + ((wm * 32 + aRowOff) * TW + aWordOff) * 4;
        uint32_t bu = bbase[buf] + ((wn * 64 + bRowOff) * TW + bWordOff) * 4;
        #pragma unroll
        for (int kk2 = 0; kk2 < 16; kk2 += 8) {
            uint32_t af[2][4], bf[8][2];
            #pragma unroll
            for (int i = 0; i < 2; i++)
                ldsm_x4(af[i][0], af[i][1], af[i][2], af[i][3],
                        au + (i * 16 * TW + kk2) * 4);
            #pragma unroll
            for (int jj = 0; jj < 4; jj++)
                ldsm_x4(bf[2 * jj][0], bf[2 * jj][1], bf[2 * jj + 1][0], bf[2 * jj + 1][1],
                        bu + (jj * 16 * TW + kk2) * 4);
            #pragma unroll
            for (int i = 0; i < 2; i++)
                #pragma unroll
                for (int j = 0; j < 8; j++)
                    mma_f16(acc[i][j], af[i], bf[j]);
        }
        if (more) {
            uint32_t* Ad = Abuf[buf ^ 1];
            uint32_t* Bd = Bbuf[buf ^ 1];
            uint4 u;
            u.x = f2h2(av[0].x, av[0].y); u.y = f2h2(av[0].z, av[0].w);
            u.z = f2h2(av[1].x, av[1].y); u.w = f2h2(av[1].z, av[1].w);
            *(uint4*)(Ad + sidx) = u;
            u.x = f2h2(av[2].x, av[2].y); u.y = f2h2(av[2].z, av[2].w);
            u.z = f2h2(av[3].x, av[3].y); u.w = f2h2(av[3].z, av[3].w);
            *(uint4*)(Ad + sidx + 4) = u;
            u.x = f2h2(bv[0].x, bv[0].y); u.y = f2h2(bv[0].z, bv[0].w);
            u.z = f2h2(bv[1].x, bv[1].y); u.w = f2h2(bv[1].z, bv[1].w);
            *(uint4*)(Bd + sidx) = u;
            u.x = f2h2(bv[2].x, bv[2].y); u.y = f2h2(bv[2].z, bv[2].w);
            u.z = f2h2(bv[3].x, bv[3].y); u.w = f2h2(bv[3].z, bv[3].w);
            *(uint4*)(Bd + sidx + 4) = u;
        }
        __syncthreads();
    }

    #pragma unroll
    for (int i = 0; i < 2; i++) {
        int row0 = m0 + wm * 32 + i * 16 + g;
        #pragma unroll
        for (int j = 0; j < 8; j++) {
            int col = n0 + wn * 64 + j * 8 + 2 * tg;
            float b0 = 0.f, b1 = 0.f;
            if (bias) { b0 = bias[col]; b1 = bias[col + 1]; }
            #pragma unroll
            for (int half = 0; half < 2; half++) {
                float v0 = acc[i][j][half * 2]     + b0;
                float v1 = acc[i][j][half * 2 + 1] + b1;
                if (act) {
                    float x3 = v0 * v0 * v0;
                    v0 = 0.5f * v0 * (1.f + tanhf(0.7978845608028654f * (v0 + 0.044715f * x3)));
                    x3 = v1 * v1 * v1;
                    v1 = 0.5f * v1 * (1.f + tanhf(0.7978845608028654f * (v1 + 0.044715f * x3)));
                }
                *(float2*)(C + (long)(row0 + half * 8) * ldc + col) = make_float2(v0, v1);
            }
        }
    }
}

// ---------------- batched weight transpose (one launch for all 9) ----------
struct TransDesc { const float* src; float* dst; int R; int C; int bstart; };
struct TransArgs { TransDesc d[9]; };

__global__ void transpose_all(TransArgs a)
{
    __shared__ float t[32][33];
    int bid = blockIdx.x;
    int i = 0;
    #pragma unroll
    for (int j = 1; j < 9; j++)
        if (bid >= a.d[j].bstart) i = j;
    const float* src = a.d[i].src;
    float* dst = a.d[i].dst;
    int R = a.d[i].R, Cc = a.d[i].C;
    int bt = bid - a.d[i].bstart;
    int tpr = Cc >> 5;
    int c0 = (bt % tpr) << 5, r0 = (bt / tpr) << 5;
    int x = threadIdx.x, y = threadIdx.y;
    #pragma unroll
    for (int k = 0; k < 32; k += 8)
        t[y + k][x] = src[(long)(r0 + y + k) * Cc + c0 + x];
    __syncthreads();
    #pragma unroll
    for (int k = 0; k < 32; k += 8)
        dst[(long)(c0 + y + k) * R + r0 + x] = t[x][y + k];
}

// ---------------- V transpose: vt[z][d][kv] = v[b*NKT+kv][h*HD+d] ----------
__global__ void vtrans(const float* __restrict__ v, float* __restrict__ vt)
{
    __shared__ float t[32][33];
    int z = blockIdx.z;
    int b = z >> 2, h = z & 3;
    int kv0 = blockIdx.x * 32, d0 = blockIdx.y * 32;
    int x = threadIdx.x, y = threadIdx.y;
    const float* src = v + ((long)b * NKT + kv0) * HID + h * HD + d0;
    #pragma unroll
    for (int i = 0; i < 32; i += 8)
        t[y + i][x] = src[(long)(y + i) * HID + x];
    __syncthreads();
    float* dst = vt + ((size_t)z * HD + d0) * NKT + kv0;
    #pragma unroll
    for (int i = 0; i < 32; i += 8)
        dst[(long)(y + i) * NKT + x] = t[x][y + i];
}

// ---------------- kv input mapping ----------------
__global__ void kvmap(const float* __restrict__ x, const float* __restrict__ Wm,
                      const float* __restrict__ bm, float* __restrict__ kv)
{
    int gg = blockIdx.x * blockDim.x + threadIdx.x;
    if (gg >= MKV * 256) return;
    int m = gg >> 8, e4 = (gg & 255) << 2;
    float4 acc = *(const float4*)(bm + e4);
    #pragma unroll
    for (int c = 0; c < 4; c++) {
        float xv = x[m * 4 + c];
        float4 w = *(const float4*)(Wm + c * EMB + e4);
        acc.x += xv * w.x; acc.y += xv * w.y; acc.z += xv * w.z; acc.w += xv * w.w;
    }
    *(float4*)(kv + (long)m * EMB + e4) = acc;
}

// ---------------- 3D RoPE (q and k in one launch) ----------------
__device__ __forceinline__ void rope_pair(float* base, int f, float t, float py, float px)
{
    int sel = (f < 22) ? 0 : ((f < 43) ? 1 : 2);
    float pos = (sel == 0) ? t : ((sel == 1) ? py : px);
    float ang = pos * exp2f(-(float)f * 0.2076205059304601f);
    float c = cosf(ang), s = sinf(ang);
    float x0 = base[f], x1 = base[f + 64];
    base[f]      = x0 * c - x1 * s;
    base[f + 64] = x1 * c + x0 * s;
}

__global__ void rope_all(float* __restrict__ q, float* __restrict__ k)
{
    const long NQE = (long)MQ * NH * 64;
    const long NKE = (long)MKV * NH * 64;
    long idx = (long)blockIdx.x * blockDim.x + threadIdx.x;
    if (idx < NQE) {
        int f = (int)(idx & 63);
        int head = (int)((idx >> 6) & 3);
        long row = idx >> 8;
        int n = (int)(row % NQT);
        int t = n / NQc, g = n % NQc;
        rope_pair(q + row * HID + head * HD, f, (float)t, (float)(g / 14), (float)(g % 14));
    } else if (idx < NQE + NKE) {
        idx -= NQE;
        int f = (int)(idx & 63);
        int head = (int)((idx >> 6) & 3);
        long row = idx >> 8;
        int n = (int)(row % NKT);
        int t = n / 64, g = n % 64;
        rope_pair(k + row * HID + head * HD, f, (float)t, (float)(g / 8), (float)(g % 8));
    }
}

// ---------------- residual add + LayerNorm ----------------
__global__ void add_ln(const float* __restrict__ X, const float* __restrict__ Y,
                       const float* __restrict__ g, const float* __restrict__ b,
                       float* __restrict__ out)
{
    long row = blockIdx.x;
    const float* x = X + row * HID;
    const float* y = Y + row * HID;
    int tid = threadIdx.x;
    float v[4]; float s = 0.f, s2 = 0.f;
    #pragma unroll
    for (int i = 0; i < 4; i++) {
        v[i] = x[tid + 128 * i] + y[tid + 128 * i];
        s += v[i]; s2 += v[i] * v[i];
    }
    __shared__ float rs[4], rs2[4];
    #pragma unroll
    for (int o = 16; o > 0; o >>= 1) {
        s  += __shfl_xor_sync(~0u, s, o);
        s2 += __shfl_xor_sync(~0u, s2, o);
    }
    if ((tid & 31) == 0) { rs[tid >> 5] = s; rs2[tid >> 5] = s2; }
    __syncthreads();
    s  = rs[0] + rs[1] + rs[2] + rs[3];
    s2 = rs2[0] + rs2[1] + rs2[2] + rs2[3];
    float mean = s * (1.f / HID);
    float var  = s2 * (1.f / HID) - mean * mean;
    float inv  = rsqrtf(var + 1e-5f);
    float* o = out + row * HID;
    #pragma unroll
    for (int i = 0; i < 4; i++) {
        int c = tid + 128 * i;
        o[c] = (v[i] - mean) * inv * g[c] + b[c];
    }
}

// ---------------- host orchestration ----------------
static inline dim3 G(int M, int N) { return dim3(N >> 7, M >> 7); }

extern "C" void kernel_launch(void* const* d_in, const int* in_sizes, int n_in,
                              void* d_out, int out_size)
{
    (void)in_sizes; (void)n_in; (void)out_size;
    const float* x_in  = (const float*)d_in[0];
    const float* slow  = (const float*)d_in[1];
    const float* Wq_in = (const float*)d_in[3];
    const float* bq_in = (const float*)d_in[4];
    const float* Wm  = (const float*)d_in[5];
    const float* bm  = (const float*)d_in[6];
    const float* Wq  = (const float*)d_in[7];
    const float* bq  = (const float*)d_in[8];
    const float* Wk  = (const float*)d_in[9];
    const float* bk  = (const float*)d_in[10];
    const float* Wv  = (const float*)d_in[11];
    const float* bv  = (const float*)d_in[12];
    const float* Wo  = (const float*)d_in[13];
    const float* bo  = (const float*)d_in[14];
    const float* g1  = (const float*)d_in[15];
    const float* be1 = (const float*)d_in[16];
    const float* W1  = (const float*)d_in[17];
    const float* b1  = (const float*)d_in[18];
    const float* W2  = (const float*)d_in[19];
    const float* b2  = (const float*)d_in[20];
    const float* g2  = (const float*)d_in[21];
    const float* be2 = (const float*)d_in[22];
    const float* M1  = (const float*)d_in[23];
    const float* bm1 = (const float*)d_in[24];
    const float* M2  = (const float*)d_in[25];
    const float* bm2 = (const float*)d_in[26];
    float* out = (float*)d_out;

    float *qin, *kv, *q, *k, *v, *o, *h, *ff, *h2, *vt;
    float *wqinT, *wqT, *wkT, *wvT, *woT, *w1T, *w2T, *m1T, *m2T;
    cudaGetSymbolAddress((void**)&qin, g_qin);
    cudaGetSymbolAddress((void**)&kv,  g_kv);
    cudaGetSymbolAddress((void**)&q,   g_q);
    cudaGetSymbolAddress((void**)&k,   g_k);
    cudaGetSymbolAddress((void**)&v,   g_v);
    cudaGetSymbolAddress((void**)&o,   g_o);
    cudaGetSymbolAddress((void**)&h,   g_h);
    cudaGetSymbolAddress((void**)&ff,  g_ff);
    cudaGetSymbolAddress((void**)&h2,  g_h2);
    cudaGetSymbolAddress((void**)&vt,  g_vt);
    cudaGetSymbolAddress((void**)&wqinT, g_wqinT);
    cudaGetSymbolAddress((void**)&wqT,   g_wqT);
    cudaGetSymbolAddress((void**)&wkT,   g_wkT);
    cudaGetSymbolAddress((void**)&wvT,   g_wvT);
    cudaGetSymbolAddress((void**)&woT,   g_woT);
    cudaGetSymbolAddress((void**)&w1T,   g_w1T);
    cudaGetSymbolAddress((void**)&w2T,   g_w2T);
    cudaGetSymbolAddress((void**)&m1T,   g_m1T);
    cudaGetSymbolAddress((void**)&m2T,   g_m2T);

    static int attr_set = 0;
    if (!attr_set) {
        cudaFuncSetAttribute(tgemm, cudaFuncAttributeMaxDynamicSharedMemorySize, GEMM_SMEM);
        cudaFuncSetAttribute(flash_attn, cudaFuncAttributeMaxDynamicSharedMemorySize, FLASH_SMEM);
        attr_set = 1;
    }

    TransArgs ta;
    ta.d[0] = { Wq_in, wqinT,  896,  512,    0 };
    ta.d[1] = { Wq,    wqT,    512,  512,  448 };
    ta.d[2] = { Wk,    wkT,   1024,  512,  704 };
    ta.d[3] = { Wv,    wvT,   1024,  512, 1216 };
    ta.d[4] = { Wo,    woT,    512,  512, 1728 };
    ta.d[5] = { W1,    w1T,    512, 1024, 1984 };
    ta.d[6] = { W2,    w2T,   1024,  512, 2496 };
    ta.d[7] = { M1,    m1T,    512, 1024, 3008 };
    ta.d[8] = { M2,    m2T,   1024,  896, 3520 };   // total 4416

    dim3 tb(32, 8);
    // 0..4
    transpose_all<<<4416, tb>>>(ta);
    kvmap<<<(MKV * 256 + 255) / 256, 256>>>(x_in, Wm, bm, kv);
    tgemm<<<G(MQ, HID), 256, GEMM_SMEM>>>(slow, wqinT, bq_in, qin,
        MQ, HID, DQ, DQ, DQ, HID, 0);
    tgemm<<<G(MKV, HID), 256, GEMM_SMEM>>>(kv, wkT, bk, k,
        MKV, HID, EMB, EMB, EMB, HID, 0);
    tgemm<<<G(MKV, HID), 256, GEMM_SMEM>>>(kv, wvT, bv, v,
        MKV, HID, EMB, EMB, EMB, HID, 0);
    // 5: q projection (MQ x 512, K=512) <- ncu profile target
    tgemm<<<G(MQ, HID), 256, GEMM_SMEM>>>(qin, wqT, bq, q,
        MQ, HID, HID, HID, HID, HID, 0);
    // RoPE (q + k fused)
    {
        long tot = (long)MQ * NH * 64 + (long)MKV * NH * 64;
        rope_all<<<(int)((tot + 255) / 256), 256>>>(q, k);
    }
    vtrans<<<dim3(NKT/32, HD/32, BB * NH), tb>>>(v, vt);
    flash_attn<<<dim3(NQT / 128, BB * NH), 256, FLASH_SMEM>>>(q, k, vt, o);
    tgemm<<<G(MQ, HID), 256, GEMM_SMEM>>>(o, woT, bo, q,
        MQ, HID, HID, HID, HID, HID, 0);
    add_ln<<<MQ, 128>>>(qin, q, g1, be1, h);
    tgemm<<<G(MQ, FFD), 256, GEMM_SMEM>>>(h, w1T, b1, ff,
        MQ, FFD, HID, HID, HID, FFD, 1);
    tgemm<<<G(MQ, HID), 256, GEMM_SMEM>>>(ff, w2T, b2, o,
        MQ, HID, FFD, FFD, FFD, HID, 0);
    add_ln<<<MQ, 128>>>(h, o, g2, be2, h2);
    tgemm<<<G(MQ, FFD), 256, GEMM_SMEM>>>(h2, m1T, bm1, ff,
        MQ, FFD, HID, HID, HID, FFD, 1);
    tgemm<<<G(MQ, OUTD), 256, GEMM_SMEM>>>(ff, m2T, bm2, out,
        MQ, OUTD, FFD, FFD, FFD, OUTD, 0);
}

// round 13
// speedup vs baseline: 1.6686x; 1.3291x over previous
#include <cuda_runtime.h>
#include <cuda_fp16.h>
#include <math.h>
#include <stdint.h>

// ---------------- problem dims ----------------
#define BB   2
#define TQc  32
#define NQc  196
#define DQ   896
#define NQT  6272
#define MQ   12544
#define NKT  2048
#define MKV  4096
#define CIN  4
#define EMB  1024
#define HID  512
#define NH   4
#define HD   128
#define FFD  1024
#define OUTD 896

// ---------------- scratch ----------------
// fp32
__device__ float g_qin[(size_t)MQ * HID];      // qin fp32 (residual)
__device__ float g_q  [(size_t)MQ * HID];      // q proj / o-proj out
__device__ float g_k  [(size_t)MKV * HID];
__device__ float g_v  [(size_t)MKV * HID];
__device__ float g_o  [(size_t)MQ * HID];      // W2 out (ffn residual)
__device__ float g_h  [(size_t)MQ * HID];      // h fp32 (residual)
__device__ float g_vt [(size_t)BB * NH * HD * NKT];
// fp16 activations
__device__ __half g_slowH[(size_t)MQ * DQ];
__device__ __half g_kvH [(size_t)MKV * EMB];
__device__ __half g_qinH[(size_t)MQ * HID];
__device__ __half g_oH  [(size_t)MQ * HID];
__device__ __half g_hH  [(size_t)MQ * HID];
__device__ __half g_ffH [(size_t)MQ * FFD];
__device__ __half g_h2H [(size_t)MQ * HID];
// fp16 transposed weights [N,K]
__device__ __half g_wqinT[512 * 896];
__device__ __half g_wqT  [512 * 512];
__device__ __half g_wkT  [512 * 1024];
__device__ __half g_wvT  [512 * 1024];
__device__ __half g_woT  [512 * 512];
__device__ __half g_w1T  [1024 * 512];
__device__ __half g_w2T  [512 * 1024];
__device__ __half g_m1T  [1024 * 512];
__device__ __half g_m2T  [896 * 1024];

// ---------------- fp16 / mma / async helpers ----------------
__device__ __forceinline__ uint32_t f2h2(float a, float b)
{
    __half2 h = __float22half2_rn(make_float2(a, b));
    return *(uint32_t*)&h;
}

__device__ __forceinline__ void mma_f16(float* d, const uint32_t* a, const uint32_t* b)
{
    asm volatile(
        "mma.sync.aligned.m16n8k16.row.col.f32.f16.f16.f32 "
        "{%0,%1,%2,%3}, {%4,%5,%6,%7}, {%8,%9}, {%0,%1,%2,%3};\n"
        : "+f"(d[0]), "+f"(d[1]), "+f"(d[2]), "+f"(d[3])
        : "r"(a[0]), "r"(a[1]), "r"(a[2]), "r"(a[3]), "r"(b[0]), "r"(b[1]));
}

__device__ __forceinline__ void ldsm_x4(uint32_t& r0, uint32_t& r1, uint32_t& r2,
                                        uint32_t& r3, uint32_t addr)
{
    asm volatile("ldmatrix.sync.aligned.m8n8.x4.shared.b16 {%0,%1,%2,%3}, [%4];"
        : "=r"(r0), "=r"(r1), "=r"(r2), "=r"(r3) : "r"(addr));
}

#define CP16(dst, src) \
    asm volatile("cp.async.ca.shared.global [%0], [%1], 16;" :: "r"(dst), "l"(src))
#define CP_COMMIT() asm volatile("cp.async.commit_group;" ::: "memory")
#define CP_WAIT(n)  asm volatile("cp.async.wait_group %0;" :: "n"(n) : "memory")

// =================================================================
// Fused flash attention (unchanged compute; fp16 output).
// Grid (NQT/128, BB*NH), 256 thr.
// =================================================================
#define FQ_W 68
#define FV_W 36
#define FLASH_WORDS (128*FQ_W + 64*FQ_W + 128*FV_W + 128*FV_W)
#define FLASH_SMEM (FLASH_WORDS * 4)   // 89088 B

__global__ void __launch_bounds__(256)
flash_attn(const float* __restrict__ gq, const float* __restrict__ gk,
           const float* __restrict__ gvt, __half* __restrict__ goh)
{
    extern __shared__ __align__(16) uint32_t sh[];
    uint32_t* Qs = sh;
    uint32_t* Ks = sh + 128 * FQ_W;
    uint32_t* Vs = Ks + 64 * FQ_W;
    uint32_t* Ps = Vs + 128 * FV_W;
    uint32_t sb = (uint32_t)__cvta_generic_to_shared(sh);
    uint32_t qbase = sb;
    uint32_t kbase = sb + 128 * FQ_W * 4;
    uint32_t vbase = kbase + 64 * FQ_W * 4;
    uint32_t pbase = vbase + 128 * FV_W * 4;

    int b = blockIdx.y >> 2, h = blockIdx.y & 3;
    int hoff = h * HD;
    long qrow0 = (long)b * NQT + (long)blockIdx.x * 128;
    long kvrow0 = (long)b * NKT;
    const float* vtbase = gvt + (size_t)blockIdx.y * HD * NKT;

    int tid = threadIdx.x, w = tid >> 5, lane = tid & 31;
    int g = lane >> 2, tg = lane & 3;
    int wr = w * 16 + g;

    int aRowOff = ((lane >> 3) & 1) * 8 + (lane & 7);
    int aWordOff = (lane >> 4) * 4;
    int bRowOff = (lane >> 4) * 8 + (lane & 7);
    int bWordOff = ((lane >> 3) & 1) * 4;

    // ---- stage Q tile (128x128) as fp16 ----
    {
        int row = tid >> 1, fseg = (tid & 1) << 6;
        const float* src = gq + (qrow0 + row) * HID + hoff + fseg;
        uint32_t* dst = Qs + row * FQ_W + (fseg >> 1);
        #pragma unroll
        for (int i = 0; i < 8; i++) {
            float4 v0 = *(const float4*)(src + i * 8);
            float4 v1 = *(const float4*)(src + i * 8 + 4);
            uint4 u;
            u.x = f2h2(v0.x, v0.y); u.y = f2h2(v0.z, v0.w);
            u.z = f2h2(v1.x, v1.y); u.w = f2h2(v1.z, v1.w);
            *(uint4*)(dst + i * 4) = u;
        }
    }

    float Oacc[16][4];
    #pragma unroll
    for (int j = 0; j < 16; j++)
        #pragma unroll
        for (int c = 0; c < 4; c++) Oacc[j][c] = 0.f;
    float m0 = -1e30f, m1 = -1e30f, l0 = 0.f, l1 = 0.f;

    const float scale = 0.08838834764831845f;
    int kvr = tid >> 2, kfs = (tid & 3) << 5;
    int vr = tid >> 1, vfs = (tid & 1) << 5;

    for (int jt = 0; jt < NKT / 64; jt++) {
        __syncthreads();
        {
            const float* ksrc = gk + (kvrow0 + jt * 64 + kvr) * HID + hoff + kfs;
            uint32_t* kd = Ks + kvr * FQ_W + (kfs >> 1);
            #pragma unroll
            for (int i = 0; i < 4; i++) {
                float4 v0 = *(const float4*)(ksrc + i * 8);
                float4 v1 = *(const float4*)(ksrc + i * 8 + 4);
                uint4 u;
                u.x = f2h2(v0.x, v0.y); u.y = f2h2(v0.z, v0.w);
                u.z = f2h2(v1.x, v1.y); u.w = f2h2(v1.z, v1.w);
                *(uint4*)(kd + i * 4) = u;
            }
            const float* vsrc = vtbase + (size_t)vr * NKT + jt * 64 + vfs;
            uint32_t* vd = Vs + vr * FV_W + (vfs >> 1);
            #pragma unroll
            for (int i = 0; i < 4; i++) {
                float4 v0 = *(const float4*)(vsrc + i * 8);
                float4 v1 = *(const float4*)(vsrc + i * 8 + 4);
                uint4 u;
                u.x = f2h2(v0.x, v0.y); u.y = f2h2(v0.z, v0.w);
                u.z = f2h2(v1.x, v1.y); u.w = f2h2(v1.z, v1.w);
                *(uint4*)(vd + i * 4) = u;
            }
        }
        __syncthreads();

        // ---- S = Q.K^T ----
        float S[8][4];
        #pragma unroll
        for (int j = 0; j < 8; j++)
            #pragma unroll
            for (int c = 0; c < 4; c++) S[j][c] = 0.f;
        {
            uint32_t qa = qbase + ((w * 16 + aRowOff) * FQ_W + aWordOff) * 4;
            uint32_t kb = kbase + ((bRowOff) * FQ_W + bWordOff) * 4;
            #pragma unroll
            for (int kk2 = 0; kk2 < 64; kk2 += 8) {
                uint32_t af[4];
                ldsm_x4(af[0], af[1], af[2], af[3], qa + kk2 * 4);
                #pragma unroll
                for (int jj = 0; jj < 4; jj++) {
                    uint32_t bf4[4];
                    ldsm_x4(bf4[0], bf4[1], bf4[2], bf4[3],
                            kb + (jj * 16 * FQ_W + kk2) * 4);
                    mma_f16(S[2 * jj],     af, bf4);
                    mma_f16(S[2 * jj + 1], af, bf4 + 2);
                }
            }
        }

        // ---- online softmax ----
        float mx0 = -1e30f, mx1 = -1e30f;
        #pragma unroll
        for (int j = 0; j < 8; j++) {
            #pragma unroll
            for (int c = 0; c < 4; c++) S[j][c] *= scale;
            mx0 = fmaxf(mx0, fmaxf(S[j][0], S[j][1]));
            mx1 = fmaxf(mx1, fmaxf(S[j][2], S[j][3]));
        }
        mx0 = fmaxf(mx0, __shfl_xor_sync(~0u, mx0, 1));
        mx0 = fmaxf(mx0, __shfl_xor_sync(~0u, mx0, 2));
        mx1 = fmaxf(mx1, __shfl_xor_sync(~0u, mx1, 1));
        mx1 = fmaxf(mx1, __shfl_xor_sync(~0u, mx1, 2));
        float mn0 = fmaxf(m0, mx0), mn1 = fmaxf(m1, mx1);
        float al0 = __expf(m0 - mn0), al1 = __expf(m1 - mn1);
        m0 = mn0; m1 = mn1;
        float sum0 = 0.f, sum1 = 0.f;
        uint32_t* prow0 = Ps + wr * FV_W;
        uint32_t* prow1 = Ps + (wr + 8) * FV_W;
        #pragma unroll
        for (int j = 0; j < 8; j++) {
            float p0 = __expf(S[j][0] - mn0);
            float p1 = __expf(S[j][1] - mn0);
            float p2 = __expf(S[j][2] - mn1);
            float p3 = __expf(S[j][3] - mn1);
            sum0 += p0 + p1; sum1 += p2 + p3;
            prow0[4 * j + tg] = f2h2(p0, p1);
            prow1[4 * j + tg] = f2h2(p2, p3);
        }
        sum0 += __shfl_xor_sync(~0u, sum0, 1);
        sum0 += __shfl_xor_sync(~0u, sum0, 2);
        sum1 += __shfl_xor_sync(~0u, sum1, 1);
        sum1 += __shfl_xor_sync(~0u, sum1, 2);
        l0 = l0 * al0 + sum0;
        l1 = l1 * al1 + sum1;
        #pragma unroll
        for (int j = 0; j < 16; j++) {
            Oacc[j][0] *= al0; Oacc[j][1] *= al0;
            Oacc[j][2] *= al1; Oacc[j][3] *= al1;
        }
        __syncwarp();

        // ---- O += P.V ----
        {
            uint32_t pa = pbase + ((w * 16 + aRowOff) * FV_W + aWordOff) * 4;
            uint32_t vb = vbase + ((bRowOff) * FV_W + bWordOff) * 4;
            #pragma unroll
            for (int kk2 = 0; kk2 < 32; kk2 += 8) {
                uint32_t af[4];
                ldsm_x4(af[0], af[1], af[2], af[3], pa + kk2 * 4);
                #pragma unroll
                for (int jj = 0; jj < 8; jj++) {
                    uint32_t bf4[4];
                    ldsm_x4(bf4[0], bf4[1], bf4[2], bf4[3],
                            vb + (jj * 16 * FV_W + kk2) * 4);
                    mma_f16(Oacc[2 * jj],     af, bf4);
                    mma_f16(Oacc[2 * jj + 1], af, bf4 + 2);
                }
            }
        }
        __syncwarp();
    }

    float inv0 = 1.f / l0, inv1 = 1.f / l1;
    __half* ob0 = goh + (qrow0 + wr) * HID + hoff;
    __half* ob1 = goh + (qrow0 + wr + 8) * HID + hoff;
    #pragma unroll
    for (int j2 = 0; j2 < 16; j2++) {
        *(uint32_t*)(ob0 + j2 * 8 + 2 * tg) = f2h2(Oacc[j2][0] * inv0, Oacc[j2][1] * inv0);
        *(uint32_t*)(ob1 + j2 * 8 + 2 * tg) = f2h2(Oacc[j2][2] * inv1, Oacc[j2][3] * inv1);
    }
}

// ---------------- fp16 GEMM: cp.async 3-stage + ldmatrix + dual output -----
#define TW 20
#define HTILE_W (128 * TW)               // words per tensor per stage
#define STAGE_W (2 * HTILE_W)            // 5120 words
#define GEMM_SMEM (3 * STAGE_W * 4)      // 61440 B

__global__ void __launch_bounds__(256, 2)
tgemm(const __half* __restrict__ A, const __half* __restrict__ Bt,
      const float* __restrict__ bias, float* __restrict__ Cf,
      __half* __restrict__ Ch,
      int M, int N, int K, int lda, int ldb, int ldc, int act)
{
    extern __shared__ __align__(16) uint32_t smem[];
    uint32_t sb = (uint32_t)__cvta_generic_to_shared(smem);

    int m0 = blockIdx.y << 7, n0 = blockIdx.x << 7;
    int tid = threadIdx.x, wid = tid >> 5, lane = tid & 31;
    int wm = wid >> 1, wn = wid & 1;
    int g = lane >> 2, tg = lane & 3;

    int lr = tid >> 1, wc = (tid & 1) << 3;
    const __half* aptr = A + (long)(m0 + lr) * lda + (wc << 1);
    const __half* bptr = Bt + (long)(n0 + lr) * ldb + (wc << 1);
    uint32_t sidx4 = (uint32_t)(lr * TW + wc) * 4;

    int aRowOff = ((lane >> 3) & 1) * 8 + (lane & 7);
    int aWordOff = (lane >> 4) * 4;
    int bRowOff = (lane >> 4) * 8 + (lane & 7);
    int bWordOff = ((lane >> 3) & 1) * 4;

    float acc[2][8][4];
    #pragma unroll
    for (int i = 0; i < 2; i++)
        #pragma unroll
        for (int j = 0; j < 8; j++)
            #pragma unroll
            for (int c = 0; c < 4; c++) acc[i][j][c] = 0.f;

    int nkt = K >> 5;

    // prologue: stages 0,1 in flight
    {
        uint32_t ab = sb + sidx4;
        uint32_t bb = ab + HTILE_W * 4;
        CP16(ab, aptr); CP16(ab + 16, aptr + 8);
        CP16(bb, bptr); CP16(bb + 16, bptr + 8);
        CP_COMMIT();
        ab = sb + STAGE_W * 4 + sidx4;
        bb = ab + HTILE_W * 4;
        CP16(ab, aptr + 32); CP16(ab + 16, aptr + 40);
        CP16(bb, bptr + 32); CP16(bb + 16, bptr + 40);
        CP_COMMIT();
    }

    int s = 0;           // stage of current tile
    int sNext = 2;       // stage for tile kt+2
    for (int kt = 0; kt < nkt; kt++) {
        if (kt + 2 < nkt) {
            int k0 = (kt + 2) << 5;
            uint32_t ab = sb + sNext * STAGE_W * 4 + sidx4;
            uint32_t bb = ab + HTILE_W * 4;
            CP16(ab, aptr + k0); CP16(ab + 16, aptr + k0 + 8);
            CP16(bb, bptr + k0); CP16(bb + 16, bptr + k0 + 8);
            CP_COMMIT();
            CP_WAIT(2);
        } else if (kt + 1 < nkt) {
            CP_WAIT(1);
        } else {
            CP_WAIT(0);
        }
        __syncthreads();

        uint32_t au = sb + s * STAGE_W * 4 + ((wm * 32 + aRowOff) * TW + aWordOff) * 4;
        uint32_t bu = sb + s * STAGE_W * 4 + HTILE_W * 4 +
                      ((wn * 64 + bRowOff) * TW + bWordOff) * 4;
        #pragma unroll
        for (int kk2 = 0; kk2 < 16; kk2 += 8) {
            uint32_t af[2][4], bf[8][2];
            #pragma unroll
            for (int i = 0; i < 2; i++)
                ldsm_x4(af[i][0], af[i][1], af[i][2], af[i][3],
                        au + (i * 16 * TW + kk2) * 4);
            #pragma unroll
            for (int jj = 0; jj < 4; jj++)
                ldsm_x4(bf[2 * jj][0], bf[2 * jj][1], bf[2 * jj + 1][0], bf[2 * jj + 1][1],
                        bu + (jj * 16 * TW + kk2) * 4);
            #pragma unroll
            for (int i = 0; i < 2; i++)
                #pragma unroll
                for (int j = 0; j < 8; j++)
                    mma_f16(acc[i][j], af[i], bf[j]);
        }
        __syncthreads();
        s = (s + 1) % 3;
        sNext = (sNext + 1) % 3;
    }

    #pragma unroll
    for (int i = 0; i < 2; i++) {
        int row0 = m0 + wm * 32 + i * 16 + g;
        #pragma unroll
        for (int j = 0; j < 8; j++) {
            int col = n0 + wn * 64 + j * 8 + 2 * tg;
            float b0 = 0.f, b1 = 0.f;
            if (bias) { b0 = bias[col]; b1 = bias[col + 1]; }
            #pragma unroll
            for (int half = 0; half < 2; half++) {
                float v0 = acc[i][j][half * 2]     + b0;
                float v1 = acc[i][j][half * 2 + 1] + b1;
                if (act) {
                    float x3 = v0 * v0 * v0;
                    v0 = 0.5f * v0 * (1.f + tanhf(0.7978845608028654f * (v0 + 0.044715f * x3)));
                    x3 = v1 * v1 * v1;
                    v1 = 0.5f * v1 * (1.f + tanhf(0.7978845608028654f * (v1 + 0.044715f * x3)));
                }
                long off = (long)(row0 + half * 8) * ldc + col;
                if (Cf) *(float2*)(Cf + off) = make_float2(v0, v1);
                if (Ch) *(uint32_t*)(Ch + off) = f2h2(v0, v1);
            }
        }
    }
}

// ---------------- batched weight transpose -> fp16 ----------------
struct TransDesc { const float* src; __half* dst; int R; int C; int bstart; };
struct TransArgs { TransDesc d[9]; };

__global__ void transpose_all(TransArgs a)
{
    __shared__ float t[32][33];
    int bid = blockIdx.x;
    int i = 0;
    #pragma unroll
    for (int j = 1; j < 9; j++)
        if (bid >= a.d[j].bstart) i = j;
    const float* src = a.d[i].src;
    __half* dst = a.d[i].dst;
    int R = a.d[i].R, Cc = a.d[i].C;
    int bt = bid - a.d[i].bstart;
    int tpr = Cc >> 5;
    int c0 = (bt % tpr) << 5, r0 = (bt / tpr) << 5;
    int x = threadIdx.x, y = threadIdx.y;
    #pragma unroll
    for (int k = 0; k < 32; k += 8)
        t[y + k][x] = src[(long)(r0 + y + k) * Cc + c0 + x];
    __syncthreads();
    #pragma unroll
    for (int k = 0; k < 32; k += 8)
        dst[(long)(c0 + y + k) * R + r0 + x] = __float2half(t[x][y + k]);
}

// ---------------- float -> half bulk convert ----------------
__global__ void to_half(const float* __restrict__ in, __half* __restrict__ out, long n)
{
    long i = ((long)blockIdx.x * blockDim.x + threadIdx.x) * 8;
    if (i >= n) return;
    float4 a = *(const float4*)(in + i);
    float4 b = *(const float4*)(in + i + 4);
    uint4 u;
    u.x = f2h2(a.x, a.y); u.y = f2h2(a.z, a.w);
    u.z = f2h2(b.x, b.y); u.w = f2h2(b.z, b.w);
    *(uint4*)(out + i) = u;
}

// ---------------- V transpose ----------------
__global__ void vtrans(const float* __restrict__ v, float* __restrict__ vt)
{
    __shared__ float t[32][33];
    int z = blockIdx.z;
    int b = z >> 2, h = z & 3;
    int kv0 = blockIdx.x * 32, d0 = blockIdx.y * 32;
    int x = threadIdx.x, y = threadIdx.y;
    const float* src = v + ((long)b * NKT + kv0) * HID + h * HD + d0;
    #pragma unroll
    for (int i = 0; i < 32; i += 8)
        t[y + i][x] = src[(long)(y + i) * HID + x];
    __syncthreads();
    float* dst = vt + ((size_t)z * HD + d0) * NKT + kv0;
    #pragma unroll
    for (int i = 0; i < 32; i += 8)
        dst[(long)(y + i) * NKT + x] = t[x][y + i];
}

// ---------------- kv input mapping -> fp16 ----------------
__global__ void kvmap(const float* __restrict__ x, const float* __restrict__ Wm,
                      const float* __restrict__ bm, __half* __restrict__ kvh)
{
    int gg = blockIdx.x * blockDim.x + threadIdx.x;
    if (gg >= MKV * 256) return;
    int m = gg >> 8, e4 = (gg & 255) << 2;
    float4 acc = *(const float4*)(bm + e4);
    #pragma unroll
    for (int c = 0; c < 4; c++) {
        float xv = x[m * 4 + c];
        float4 w = *(const float4*)(Wm + c * EMB + e4);
        acc.x += xv * w.x; acc.y += xv * w.y; acc.z += xv * w.z; acc.w += xv * w.w;
    }
    uint2 st;
    st.x = f2h2(acc.x, acc.y); st.y = f2h2(acc.z, acc.w);
    *(uint2*)(kvh + (long)m * EMB + e4) = st;
}

// ---------------- 3D RoPE (fused q+k) ----------------
__device__ __forceinline__ void rope_pair(float* base, int f, float t, float py, float px)
{
    int sel = (f < 22) ? 0 : ((f < 43) ? 1 : 2);
    float pos = (sel == 0) ? t : ((sel == 1) ? py : px);
    float ang = pos * exp2f(-(float)f * 0.2076205059304601f);
    float c = cosf(ang), s = sinf(ang);
    float x0 = base[f], x1 = base[f + 64];
    base[f]      = x0 * c - x1 * s;
    base[f + 64] = x1 * c + x0 * s;
}

__global__ void rope_all(float* __restrict__ q, float* __restrict__ k)
{
    const long NQE = (long)MQ * NH * 64;
    const long NKE = (long)MKV * NH * 64;
    long idx = (long)blockIdx.x * blockDim.x + threadIdx.x;
    if (idx < NQE) {
        int f = (int)(idx & 63);
        int head = (int)((idx >> 6) & 3);
        long row = idx >> 8;
        int n = (int)(row % NQT);
        int t = n / NQc, g = n % NQc;
        rope_pair(q + row * HID + head * HD, f, (float)t, (float)(g / 14), (float)(g % 14));
    } else if (idx < NQE + NKE) {
        idx -= NQE;
        int f = (int)(idx & 63);
        int head = (int)((idx >> 6) & 3);
        long row = idx >> 8;
        int n = (int)(row % NKT);
        int t = n / 64, g = n % 64;
        rope_pair(k + row * HID + head * HD, f, (float)t, (float)(g / 8), (float)(g % 8));
    }
}

// ---------------- residual add + LayerNorm, dual output ----------------
__global__ void add_ln(const float* __restrict__ X, const float* __restrict__ Y,
                       const float* __restrict__ g, const float* __restrict__ b,
                       float* __restrict__ outF, __half* __restrict__ outH)
{
    long row = blockIdx.x;
    const float* x = X + row * HID;
    const float* y = Y + row * HID;
    int tid = threadIdx.x;
    float v[4]; float s = 0.f, s2 = 0.f;
    #pragma unroll
    for (int i = 0; i < 4; i++) {
        v[i] = x[tid + 128 * i] + y[tid + 128 * i];
        s += v[i]; s2 += v[i] * v[i];
    }
    __shared__ float rs[4], rs2[4];
    #pragma unroll
    for (int o = 16; o > 0; o >>= 1) {
        s  += __shfl_xor_sync(~0u, s, o);
        s2 += __shfl_xor_sync(~0u, s2, o);
    }
    if ((tid & 31) == 0) { rs[tid >> 5] = s; rs2[tid >> 5] = s2; }
    __syncthreads();
    s  = rs[0] + rs[1] + rs[2] + rs[3];
    s2 = rs2[0] + rs2[1] + rs2[2] + rs2[3];
    float mean = s * (1.f / HID);
    float var  = s2 * (1.f / HID) - mean * mean;
    float inv  = rsqrtf(var + 1e-5f);
    #pragma unroll
    for (int i = 0; i < 4; i++) {
        int c = tid + 128 * i;
        float val = (v[i] - mean) * inv * g[c] + b[c];
        if (outF) outF[row * HID + c] = val;
        if (outH) outH[row * HID + c] = __float2half(val);
    }
}

// ---------------- host orchestration ----------------
static inline dim3 G(int M, int N) { return dim3(N >> 7, M >> 7); }

extern "C" void kernel_launch(void* const* d_in, const int* in_sizes, int n_in,
                              void* d_out, int out_size)
{
    (void)in_sizes; (void)n_in; (void)out_size;
    const float* x_in  = (const float*)d_in[0];
    const float* slow  = (const float*)d_in[1];
    const float* Wq_in = (const float*)d_in[3];
    const float* bq_in = (const float*)d_in[4];
    const float* Wm  = (const float*)d_in[5];
    const float* bm  = (const float*)d_in[6];
    const float* Wq  = (const float*)d_in[7];
    const float* bq  = (const float*)d_in[8];
    const float* Wk  = (const float*)d_in[9];
    const float* bk  = (const float*)d_in[10];
    const float* Wv  = (const float*)d_in[11];
    const float* bv  = (const float*)d_in[12];
    const float* Wo  = (const float*)d_in[13];
    const float* bo  = (const float*)d_in[14];
    const float* g1  = (const float*)d_in[15];
    const float* be1 = (const float*)d_in[16];
    const float* W1  = (const float*)d_in[17];
    const float* b1  = (const float*)d_in[18];
    const float* W2  = (const float*)d_in[19];
    const float* b2  = (const float*)d_in[20];
    const float* g2  = (const float*)d_in[21];
    const float* be2 = (const float*)d_in[22];
    const float* M1  = (const float*)d_in[23];
    const float* bm1 = (const float*)d_in[24];
    const float* M2  = (const float*)d_in[25];
    const float* bm2 = (const float*)d_in[26];
    float* out = (float*)d_out;

    float *qinF, *q, *k, *v, *o, *h, *vt;
    __half *slowH, *kvH, *qinH, *oH, *hH, *ffH, *h2H;
    __half *wqinT, *wqT, *wkT, *wvT, *woT, *w1T, *w2T, *m1T, *m2T;
    cudaGetSymbolAddress((void**)&qinF, g_qin);
    cudaGetSymbolAddress((void**)&q,    g_q);
    cudaGetSymbolAddress((void**)&k,    g_k);
    cudaGetSymbolAddress((void**)&v,    g_v);
    cudaGetSymbolAddress((void**)&o,    g_o);
    cudaGetSymbolAddress((void**)&h,    g_h);
    cudaGetSymbolAddress((void**)&vt,   g_vt);
    cudaGetSymbolAddress((void**)&slowH, g_slowH);
    cudaGetSymbolAddress((void**)&kvH,   g_kvH);
    cudaGetSymbolAddress((void**)&qinH,  g_qinH);
    cudaGetSymbolAddress((void**)&oH,    g_oH);
    cudaGetSymbolAddress((void**)&hH,    g_hH);
    cudaGetSymbolAddress((void**)&ffH,   g_ffH);
    cudaGetSymbolAddress((void**)&h2H,   g_h2H);
    cudaGetSymbolAddress((void**)&wqinT, g_wqinT);
    cudaGetSymbolAddress((void**)&wqT,   g_wqT);
    cudaGetSymbolAddress((void**)&wkT,   g_wkT);
    cudaGetSymbolAddress((void**)&wvT,   g_wvT);
    cudaGetSymbolAddress((void**)&woT,   g_woT);
    cudaGetSymbolAddress((void**)&w1T,   g_w1T);
    cudaGetSymbolAddress((void**)&w2T,   g_w2T);
    cudaGetSymbolAddress((void**)&m1T,   g_m1T);
    cudaGetSymbolAddress((void**)&m2T,   g_m2T);

    static int attr_set = 0;
    if (!attr_set) {
        cudaFuncSetAttribute(tgemm, cudaFuncAttributeMaxDynamicSharedMemorySize, GEMM_SMEM);
        cudaFuncSetAttribute(flash_attn, cudaFuncAttributeMaxDynamicSharedMemorySize, FLASH_SMEM);
        attr_set = 1;
    }

    TransArgs ta;
    ta.d[0] = { Wq_in, wqinT,  896,  512,    0 };
    ta.d[1] = { Wq,    wqT,    512,  512,  448 };
    ta.d[2] = { Wk,    wkT,   1024,  512,  704 };
    ta.d[3] = { Wv,    wvT,   1024,  512, 1216 };
    ta.d[4] = { Wo,    woT,    512,  512, 1728 };
    ta.d[5] = { W1,    w1T,    512, 1024, 1984 };
    ta.d[6] = { W2,    w2T,   1024,  512, 2496 };
    ta.d[7] = { M1,    m1T,    512, 1024, 3008 };
    ta.d[8] = { M2,    m2T,   1024,  896, 3520 };   // total 4416

    dim3 tb(32, 8);
    // launches 0..4
    transpose_all<<<4416, tb>>>(ta);
    to_half<<<(int)(((long)MQ * DQ / 8 + 255) / 256), 256>>>(slow, slowH, (long)MQ * DQ);
    kvmap<<<(MKV * 256 + 255) / 256, 256>>>(x_in, Wm, bm, kvH);
    tgemm<<<G(MQ, HID), 256, GEMM_SMEM>>>(slowH, wqinT, bq_in, qinF, qinH,
        MQ, HID, DQ, DQ, DQ, HID, 0);
    tgemm<<<G(MKV, HID), 256, GEMM_SMEM>>>(kvH, wkT, bk, k, (  __half*)0,
        MKV, HID, EMB, EMB, EMB, HID, 0);
    // 5: v projection (grid 128, K=1024)  <- ncu profile target
    tgemm<<<G(MKV, HID), 256, GEMM_SMEM>>>(kvH, wvT, bv, v, (__half*)0,
        MKV, HID, EMB, EMB, EMB, HID, 0);
    tgemm<<<G(MQ, HID), 256, GEMM_SMEM>>>(qinH, wqT, bq, q, (__half*)0,
        MQ, HID, HID, HID, HID, HID, 0);
    {
        long tot = (long)MQ * NH * 64 + (long)MKV * NH * 64;
        rope_all<<<(int)((tot + 255) / 256), 256>>>(q, k);
    }
    vtrans<<<dim3(NKT/32, HD/32, BB * NH), tb>>>(v, vt);
    flash_attn<<<dim3(NQT / 128, BB * NH), 256, FLASH_SMEM>>>(q, k, vt, oH);
    // o-proj -> g_q (fp32)
    tgemm<<<G(MQ, HID), 256, GEMM_SMEM>>>(oH, woT, bo, q, (__half*)0,
        MQ, HID, HID, HID, HID, HID, 0);
    add_ln<<<MQ, 128>>>(qinF, q, g1, be1, h, hH);
    tgemm<<<G(MQ, FFD), 256, GEMM_SMEM>>>(hH, w1T, b1, (float*)0, ffH,
        MQ, FFD, HID, HID, HID, FFD, 1);
    tgemm<<<G(MQ, HID), 256, GEMM_SMEM>>>(ffH, w2T, b2, o, (__half*)0,
        MQ, HID, FFD, FFD, FFD, HID, 0);
    add_ln<<<MQ, 128>>>(h, o, g2, be2, (float*)0, h2H);
    tgemm<<<G(MQ, FFD), 256, GEMM_SMEM>>>(h2H, m1T, bm1, (float*)0, ffH,
        MQ, FFD, HID, HID, HID, FFD, 1);
    tgemm<<<G(MQ, OUTD), 256, GEMM_SMEM>>>(ffH, m2T, bm2, out, (__half*)0,
        MQ, OUTD, FFD, FFD, FFD, OUTD, 0);
}

// round 14
// speedup vs baseline: 1.9883x; 1.1916x over previous
#include <cuda_runtime.h>
#include <cuda_fp16.h>
#include <math.h>
#include <stdint.h>

// ---------------- problem dims ----------------
#define BB   2
#define TQc  32
#define NQc  196
#define DQ   896
#define NQT  6272
#define MQ   12544
#define NKT  2048
#define MKV  4096
#define CIN  4
#define EMB  1024
#define HID  512
#define NH   4
#define HD   128
#define FFD  1024
#define OUTD 896

// ---------------- scratch ----------------
// fp32
__device__ float g_qin[(size_t)MQ * HID];        // qin fp32 (residual)
__device__ float g_q  [(size_t)MQ * HID];        // q proj / o-proj out
__device__ float g_kvP[(size_t)MKV * 1024];      // merged k|v projection out
__device__ float g_o  [(size_t)MQ * HID];        // W2 out (ffn residual)
__device__ float g_h  [(size_t)MQ * HID];        // h fp32 (residual)
__device__ float g_bkv[1024];                    // concat bias bk|bv
// fp16 activations
__device__ __half g_slowH[(size_t)MQ * DQ];
__device__ __half g_kvH [(size_t)MKV * EMB];
__device__ __half g_qinH[(size_t)MQ * HID];
__device__ __half g_qH  [(size_t)MQ * HID];      // rope'd q fp16
__device__ __half g_kH  [(size_t)MKV * HID];     // rope'd k fp16
__device__ __half g_vtH [(size_t)BB * NH * HD * NKT];  // transposed v fp16
__device__ __half g_oH  [(size_t)MQ * HID];
__device__ __half g_hH  [(size_t)MQ * HID];
__device__ __half g_ffH [(size_t)MQ * FFD];
__device__ __half g_h2H [(size_t)MQ * HID];
// fp16 transposed weights [N,K]
__device__ __half g_wqinT[512 * 896];
__device__ __half g_wqT  [512 * 512];
__device__ __half g_wkvT [1024 * 1024];          // k rows 0-511, v rows 512-1023
__device__ __half g_woT  [512 * 512];
__device__ __half g_w1T  [1024 * 512];
__device__ __half g_w2T  [512 * 1024];
__device__ __half g_m1T  [1024 * 512];
__device__ __half g_m2T  [896 * 1024];

// ---------------- helpers ----------------
__device__ __forceinline__ uint32_t f2h2(float a, float b)
{
    __half2 h = __float22half2_rn(make_float2(a, b));
    return *(uint32_t*)&h;
}

__device__ __forceinline__ void mma_f16(float* d, const uint32_t* a, const uint32_t* b)
{
    asm volatile(
        "mma.sync.aligned.m16n8k16.row.col.f32.f16.f16.f32 "
        "{%0,%1,%2,%3}, {%4,%5,%6,%7}, {%8,%9}, {%0,%1,%2,%3};\n"
        : "+f"(d[0]), "+f"(d[1]), "+f"(d[2]), "+f"(d[3])
        : "r"(a[0]), "r"(a[1]), "r"(a[2]), "r"(a[3]), "r"(b[0]), "r"(b[1]));
}

__device__ __forceinline__ void ldsm_x4(uint32_t& r0, uint32_t& r1, uint32_t& r2,
                                        uint32_t& r3, uint32_t addr)
{
    asm volatile("ldmatrix.sync.aligned.m8n8.x4.shared.b16 {%0,%1,%2,%3}, [%4];"
        : "=r"(r0), "=r"(r1), "=r"(r2), "=r"(r3) : "r"(addr));
}

#define CP16(dst, src) \
    asm volatile("cp.async.cg.shared.global [%0], [%1], 16;" :: "r"(dst), "l"(src))
#define CP_COMMIT() asm volatile("cp.async.commit_group;" ::: "memory")
#define CP_WAIT(n)  asm volatile("cp.async.wait_group %0;" :: "n"(n) : "memory")

// =================================================================
// Fused flash attention: fp16 inputs staged via cp.async.
// Grid (NQT/128, BB*NH), 256 thr (8 warps x 16 q-rows).
// =================================================================
#define FQ_W 68
#define FV_W 36
#define FLASH_WORDS (128*FQ_W + 64*FQ_W + 128*FV_W + 128*FV_W)
#define FLASH_SMEM (FLASH_WORDS * 4)   // 89088 B

__global__ void __launch_bounds__(256)
flash_attn(const __half* __restrict__ gqh, const __half* __restrict__ gkh,
           const __half* __restrict__ gvth, __half* __restrict__ goh)
{
    extern __shared__ __align__(16) uint32_t sh[];
    uint32_t* Ps = sh + 128 * FQ_W + 64 * FQ_W + 128 * FV_W;
    uint32_t sb = (uint32_t)__cvta_generic_to_shared(sh);
    uint32_t qbase = sb;
    uint32_t kbase = sb + 128 * FQ_W * 4;
    uint32_t vbase = kbase + 64 * FQ_W * 4;
    uint32_t pbase = vbase + 128 * FV_W * 4;

    int b = blockIdx.y >> 2, h = blockIdx.y & 3;
    int hoff = h * HD;
    long qrow0 = (long)b * NQT + (long)blockIdx.x * 128;
    long kvrow0 = (long)b * NKT;
    const __half* vtb = gvth + (size_t)blockIdx.y * HD * NKT;

    int tid = threadIdx.x, w = tid >> 5, lane = tid & 31;
    int g = lane >> 2, tg = lane & 3;
    int wr = w * 16 + g;

    int aRowOff = ((lane >> 3) & 1) * 8 + (lane & 7);
    int aWordOff = (lane >> 4) * 4;
    int bRowOff = (lane >> 4) * 8 + (lane & 7);
    int bWordOff = ((lane >> 3) & 1) * 4;

    // ---- stage Q tile (128 rows x 128 halves) via cp.async ----
    {
        int row = tid >> 1, cs = (tid & 1) * 8;
        const __half* src = gqh + (qrow0 + row) * HID + hoff + cs * 8;
        uint32_t dst = qbase + (uint32_t)(row * FQ_W + cs * 4) * 4;
        #pragma unroll
        for (int i = 0; i < 8; i++) CP16(dst + i * 16, src + i * 8);
        CP_COMMIT();
    }

    float Oacc[16][4];
    #pragma unroll
    for (int j = 0; j < 16; j++)
        #pragma unroll
        for (int c = 0; c < 4; c++) Oacc[j][c] = 0.f;
    float m0 = -1e30f, m1 = -1e30f, l0 = 0.f, l1 = 0.f;

    const float scale = 0.08838834764831845f;
    int kr = tid >> 2, kc = (tid & 3) * 4;
    int vr = tid >> 1, vc = (tid & 1) * 4;

    for (int jt = 0; jt < NKT / 64; jt++) {
        __syncthreads();
        // ---- stage K (64x128) + V^T (128x64) via cp.async ----
        {
            const __half* ks = gkh + (kvrow0 + jt * 64 + kr) * HID + hoff + kc * 8;
            uint32_t kd = kbase + (uint32_t)(kr * FQ_W + kc * 4) * 4;
            #pragma unroll
            for (int i = 0; i < 4; i++) CP16(kd + i * 16, ks + i * 8);
            const __half* vs = vtb + (size_t)vr * NKT + jt * 64 + vc * 8;
            uint32_t vd = vbase + (uint32_t)(vr * FV_W + vc * 4) * 4;
            #pragma unroll
            for (int i = 0; i < 4; i++) CP16(vd + i * 16, vs + i * 8);
            CP_COMMIT();
            CP_WAIT(0);
        }
        __syncthreads();

        // ---- S = Q.K^T ----
        float S[8][4];
        #pragma unroll
        for (int j = 0; j < 8; j++)
            #pragma unroll
            for (int c = 0; c < 4; c++) S[j][c] = 0.f;
        {
            uint32_t qa = qbase + ((w * 16 + aRowOff) * FQ_W + aWordOff) * 4;
            uint32_t kb = kbase + ((bRowOff) * FQ_W + bWordOff) * 4;
            #pragma unroll
            for (int kk2 = 0; kk2 < 64; kk2 += 8) {
                uint32_t af[4];
                ldsm_x4(af[0], af[1], af[2], af[3], qa + kk2 * 4);
                #pragma unroll
                for (int jj = 0; jj < 4; jj++) {
                    uint32_t bf4[4];
                    ldsm_x4(bf4[0], bf4[1], bf4[2], bf4[3],
                            kb + (jj * 16 * FQ_W + kk2) * 4);
                    mma_f16(S[2 * jj],     af, bf4);
                    mma_f16(S[2 * jj + 1], af, bf4 + 2);
                }
            }
        }

        // ---- online softmax ----
        float mx0 = -1e30f, mx1 = -1e30f;
        #pragma unroll
        for (int j = 0; j < 8; j++) {
            #pragma unroll
            for (int c = 0; c < 4; c++) S[j][c] *= scale;
            mx0 = fmaxf(mx0, fmaxf(S[j][0], S[j][1]));
            mx1 = fmaxf(mx1, fmaxf(S[j][2], S[j][3]));
        }
        mx0 = fmaxf(mx0, __shfl_xor_sync(~0u, mx0, 1));
        mx0 = fmaxf(mx0, __shfl_xor_sync(~0u, mx0, 2));
        mx1 = fmaxf(mx1, __shfl_xor_sync(~0u, mx1, 1));
        mx1 = fmaxf(mx1, __shfl_xor_sync(~0u, mx1, 2));
        float mn0 = fmaxf(m0, mx0), mn1 = fmaxf(m1, mx1);
        float al0 = __expf(m0 - mn0), al1 = __expf(m1 - mn1);
        m0 = mn0; m1 = mn1;
        float sum0 = 0.f, sum1 = 0.f;
        uint32_t* prow0 = Ps + wr * FV_W;
        uint32_t* prow1 = Ps + (wr + 8) * FV_W;
        #pragma unroll
        for (int j = 0; j < 8; j++) {
            float p0 = __expf(S[j][0] - mn0);
            float p1 = __expf(S[j][1] - mn0);
            float p2 = __expf(S[j][2] - mn1);
            float p3 = __expf(S[j][3] - mn1);
            sum0 += p0 + p1; sum1 += p2 + p3;
            prow0[4 * j + tg] = f2h2(p0, p1);
            prow1[4 * j + tg] = f2h2(p2, p3);
        }
        sum0 += __shfl_xor_sync(~0u, sum0, 1);
        sum0 += __shfl_xor_sync(~0u, sum0, 2);
        sum1 += __shfl_xor_sync(~0u, sum1, 1);
        sum1 += __shfl_xor_sync(~0u, sum1, 2);
        l0 = l0 * al0 + sum0;
        l1 = l1 * al1 + sum1;
        #pragma unroll
        for (int j = 0; j < 16; j++) {
            Oacc[j][0] *= al0; Oacc[j][1] *= al0;
            Oacc[j][2] *= al1; Oacc[j][3] *= al1;
        }
        __syncwarp();

        // ---- O += P.V ----
        {
            uint32_t pa = pbase + ((w * 16 + aRowOff) * FV_W + aWordOff) * 4;
            uint32_t vb = vbase + ((bRowOff) * FV_W + bWordOff) * 4;
            #pragma unroll
            for (int kk2 = 0; kk2 < 32; kk2 += 8) {
                uint32_t af[4];
                ldsm_x4(af[0], af[1], af[2], af[3], pa + kk2 * 4);
                #pragma unroll
                for (int jj = 0; jj < 8; jj++) {
                    uint32_t bf4[4];
                    ldsm_x4(bf4[0], bf4[1], bf4[2], bf4[3],
                            vb + (jj * 16 * FV_W + kk2) * 4);
                    mma_f16(Oacc[2 * jj],     af, bf4);
                    mma_f16(Oacc[2 * jj + 1], af, bf4 + 2);
                }
            }
        }
        __syncwarp();
    }

    float inv0 = 1.f / l0, inv1 = 1.f / l1;
    __half* ob0 = goh + (qrow0 + wr) * HID + hoff;
    __half* ob1 = goh + (qrow0 + wr + 8) * HID + hoff;
    #pragma unroll
    for (int j2 = 0; j2 < 16; j2++) {
        *(uint32_t*)(ob0 + j2 * 8 + 2 * tg) = f2h2(Oacc[j2][0] * inv0, Oacc[j2][1] * inv0);
        *(uint32_t*)(ob1 + j2 * 8 + 2 * tg) = f2h2(Oacc[j2][2] * inv1, Oacc[j2][3] * inv1);
    }
}

// ---------------- fp16 GEMM: cp.async 3-stage + ldmatrix + dual output -----
#define TW 20
#define HTILE_W (128 * TW)
#define STAGE_W (2 * HTILE_W)
#define GEMM_SMEM (3 * STAGE_W * 4)      // 61440 B

__global__ void __launch_bounds__(256, 2)
tgemm(const __half* __restrict__ A, const __half* __restrict__ Bt,
      const float* __restrict__ bias, float* __restrict__ Cf,
      __half* __restrict__ Ch,
      int M, int N, int K, int lda, int ldb, int ldc, int act)
{
    extern __shared__ __align__(16) uint32_t smem[];
    uint32_t sb = (uint32_t)__cvta_generic_to_shared(smem);

    int m0 = blockIdx.y << 7, n0 = blockIdx.x << 7;
    int tid = threadIdx.x, wid = tid >> 5, lane = tid & 31;
    int wm = wid >> 1, wn = wid & 1;
    int g = lane >> 2, tg = lane & 3;

    int lr = tid >> 1, wc = (tid & 1) << 3;
    const __half* aptr = A + (long)(m0 + lr) * lda + (wc << 1);
    const __half* bptr = Bt + (long)(n0 + lr) * ldb + (wc << 1);
    uint32_t sidx4 = (uint32_t)(lr * TW + wc) * 4;

    int aRowOff = ((lane >> 3) & 1) * 8 + (lane & 7);
    int aWordOff = (lane >> 4) * 4;
    int bRowOff = (lane >> 4) * 8 + (lane & 7);
    int bWordOff = ((lane >> 3) & 1) * 4;

    float acc[2][8][4];
    #pragma unroll
    for (int i = 0; i < 2; i++)
        #pragma unroll
        for (int j = 0; j < 8; j++)
            #pragma unroll
            for (int c = 0; c < 4; c++) acc[i][j][c] = 0.f;

    int nkt = K >> 5;

    {
        uint32_t ab = sb + sidx4;
        uint32_t bb = ab + HTILE_W * 4;
        CP16(ab, aptr); CP16(ab + 16, aptr + 8);
        CP16(bb, bptr); CP16(bb + 16, bptr + 8);
        CP_COMMIT();
        ab = sb + STAGE_W * 4 + sidx4;
        bb = ab + HTILE_W * 4;
        CP16(ab, aptr + 32); CP16(ab + 16, aptr + 40);
        CP16(bb, bptr + 32); CP16(bb + 16, bptr + 40);
        CP_COMMIT();
    }

    int s = 0, sNext = 2;
    for (int kt = 0; kt < nkt; kt++) {
        if (kt + 2 < nkt) {
            int k0 = (kt + 2) << 5;
            uint32_t ab = sb + sNext * STAGE_W * 4 + sidx4;
            uint32_t bb = ab + HTILE_W * 4;
            CP16(ab, aptr + k0); CP16(ab + 16, aptr + k0 + 8);
            CP16(bb, bptr + k0); CP16(bb + 16, bptr + k0 + 8);
            CP_COMMIT();
            CP_WAIT(2);
        } else if (kt + 1 < nkt) {
            CP_WAIT(1);
        } else {
            CP_WAIT(0);
        }
        __syncthreads();

        uint32_t au = sb + s * STAGE_W * 4 + ((wm * 32 + aRowOff) * TW + aWordOff) * 4;
        uint32_t bu = sb + s * STAGE_W * 4 + HTILE_W * 4 +
                      ((wn * 64 + bRowOff) * TW + bWordOff) * 4;
        #pragma unroll
        for (int kk2 = 0; kk2 < 16; kk2 += 8) {
            uint32_t af[2][4], bf[8][2];
            #pragma unroll
            for (int i = 0; i < 2; i++)
                ldsm_x4(af[i][0], af[i][1], af[i][2], af[i][3],
                        au + (i * 16 * TW + kk2) * 4);
            #pragma unroll
            for (int jj = 0; jj < 4; jj++)
                ldsm_x4(bf[2 * jj][0], bf[2 * jj][1], bf[2 * jj + 1][0], bf[2 * jj + 1][1],
                        bu + (jj * 16 * TW + kk2) * 4);
            #pragma unroll
            for (int i = 0; i < 2; i++)
                #pragma unroll
                for (int j = 0; j < 8; j++)
                    mma_f16(acc[i][j], af[i], bf[j]);
        }
        __syncthreads();
        s = (s + 1) % 3;
        sNext = (sNext + 1) % 3;
    }

    #pragma unroll
    for (int i = 0; i < 2; i++) {
        int row0 = m0 + wm * 32 + i * 16 + g;
        #pragma unroll
        for (int j = 0; j < 8; j++) {
            int col = n0 + wn * 64 + j * 8 + 2 * tg;
            float b0 = 0.f, b1 = 0.f;
            if (bias) { b0 = bias[col]; b1 = bias[col + 1]; }
            #pragma unroll
            for (int half = 0; half < 2; half++) {
                float v0 = acc[i][j][half * 2]     + b0;
                float v1 = acc[i][j][half * 2 + 1] + b1;
                if (act) {
                    float x3 = v0 * v0 * v0;
                    v0 = 0.5f * v0 * (1.f + tanhf(0.7978845608028654f * (v0 + 0.044715f * x3)));
                    x3 = v1 * v1 * v1;
                    v1 = 0.5f * v1 * (1.f + tanhf(0.7978845608028654f * (v1 + 0.044715f * x3)));
                }
                long off = (long)(row0 + half * 8) * ldc + col;
                if (Cf) *(float2*)(Cf + off) = make_float2(v0, v1);
                if (Ch) *(uint32_t*)(Ch + off) = f2h2(v0, v1);
            }
        }
    }
}

// ---------------- batched weight transpose -> fp16 ----------------
struct TransDesc { const float* src; __half* dst; int R; int C; int bstart; };
struct TransArgs { TransDesc d[9]; };

__global__ void transpose_all(TransArgs a)
{
    __shared__ float t[32][33];
    int bid = blockIdx.x;
    int i = 0;
    #pragma unroll
    for (int j = 1; j < 9; j++)
        if (bid >= a.d[j].bstart) i = j;
    const float* src = a.d[i].src;
    __half* dst = a.d[i].dst;
    int R = a.d[i].R, Cc = a.d[i].C;
    int bt = bid - a.d[i].bstart;
    int tpr = Cc >> 5;
    int c0 = (bt % tpr) << 5, r0 = (bt / tpr) << 5;
    int x = threadIdx.x, y = threadIdx.y;
    #pragma unroll
    for (int k = 0; k < 32; k += 8)
        t[y + k][x] = src[(long)(r0 + y + k) * Cc + c0 + x];
    __syncthreads();
    #pragma unroll
    for (int k = 0; k < 32; k += 8)
        dst[(long)(c0 + y + k) * R + r0 + x] = __float2half(t[x][y + k]);
}

// ---------------- float -> half bulk convert ----------------
__global__ void to_half(const float* __restrict__ in, __half* __restrict__ out, long n)
{
    long i = ((long)blockIdx.x * blockDim.x + threadIdx.x) * 8;
    if (i >= n) return;
    float4 a = *(const float4*)(in + i);
    float4 b = *(const float4*)(in + i + 4);
    uint4 u;
    u.x = f2h2(a.x, a.y); u.y = f2h2(a.z, a.w);
    u.z = f2h2(b.x, b.y); u.w = f2h2(b.z, b.w);
    *(uint4*)(out + i) = u;
}

// ---------------- concat bias ----------------
__global__ void concat_bias(const float* __restrict__ bk, const float* __restrict__ bv,
                            float* __restrict__ bkv)
{
    int i = blockIdx.x * 256 + threadIdx.x;
    if (i < 512) bkv[i] = bk[i];
    else if (i < 1024) bkv[i] = bv[i - 512];
}

// ---------------- V transpose (from merged kvP, cols 512..1023) -> fp16 ----
__global__ void vtrans(const float* __restrict__ kvP, __half* __restrict__ vth)
{
    __shared__ float t[32][33];
    int z = blockIdx.z;
    int b = z >> 2, h = z & 3;
    int kv0 = blockIdx.x * 32, d0 = blockIdx.y * 32;
    int x = threadIdx.x, y = threadIdx.y;
    const float* src = kvP + ((long)b * NKT + kv0) * 1024 + 512 + h * HD + d0;
    #pragma unroll
    for (int i = 0; i < 32; i += 8)
        t[y + i][x] = src[(long)(y + i) * 1024 + x];
    __syncthreads();
    __half* dst = vth + ((size_t)z * HD + d0) * NKT + kv0;
    #pragma unroll
    for (int i = 0; i < 32; i += 8)
        dst[(long)(y + i) * NKT + x] = __float2half(t[x][y + i]);
}

// ---------------- kv input mapping -> fp16 ----------------
__global__ void kvmap(const float* __restrict__ x, const float* __restrict__ Wm,
                      const float* __restrict__ bm, __half* __restrict__ kvh)
{
    int gg = blockIdx.x * blockDim.x + threadIdx.x;
    if (gg >= MKV * 256) return;
    int m = gg >> 8, e4 = (gg & 255) << 2;
    float4 acc = *(const float4*)(bm + e4);
    #pragma unroll
    for (int c = 0; c < 4; c++) {
        float xv = x[m * 4 + c];
        float4 w = *(const float4*)(Wm + c * EMB + e4);
        acc.x += xv * w.x; acc.y += xv * w.y; acc.z += xv * w.z; acc.w += xv * w.w;
    }
    uint2 st;
    st.x = f2h2(acc.x, acc.y); st.y = f2h2(acc.z, acc.w);
    *(uint2*)(kvh + (long)m * EMB + e4) = st;
}

// ---------------- 3D RoPE: fp32 in -> fp16 out, q + k fused ----------------
__global__ void rope_all(const float* __restrict__ q, __half* __restrict__ qh,
                         const float* __restrict__ kvP, __half* __restrict__ kh)
{
    const long NQE = (long)MQ * NH * 64;
    const long NKE = (long)MKV * NH * 64;
    long idx = (long)blockIdx.x * blockDim.x + threadIdx.x;
    if (idx >= NQE + NKE) return;
    int f, head; long row;
    float pt, py, px;
    const float* src;
    __half* dst;
    if (idx < NQE) {
        f = (int)(idx & 63);
        head = (int)((idx >> 6) & 3);
        row = idx >> 8;
        int n = (int)(row % NQT);
        pt = (float)(n / NQc); py = (float)((n % NQc) / 14); px = (float)((n % NQc) % 14);
        src = q + row * HID + head * HD;
        dst = qh + row * HID + head * HD;
    } else {
        idx -= NQE;
        f = (int)(idx & 63);
        head = (int)((idx >> 6) & 3);
        row = idx >> 8;
        int n = (int)(row % NKT);
        pt = (float)(n / 64); py = (float)((n % 64) / 8); px = (float)((n % 64) % 8);
        src = kvP + row * 1024 + head * HD;
        dst = kh + row * HID + head * HD;
    }
    int sel = (f < 22) ? 0 : ((f < 43) ? 1 : 2);
    float pos = (sel == 0) ? pt : ((sel == 1) ? py : px);
    float ang = pos * exp2f(-(float)f * 0.2076205059304601f);
    float c = cosf(ang), s = sinf(ang);
    float x0 = src[f], x1 = src[f + 64];
    dst[f]      = __float2half(x0 * c - x1 * s);
    dst[f + 64] = __float2half(x1 * c + x0 * s);
}

// ---------------- residual add + LayerNorm, dual output ----------------
__global__ void add_ln(const float* __restrict__ X, const float* __restrict__ Y,
                       const float* __restrict__ g, const float* __restrict__ b,
                       float* __restrict__ outF, __half* __restrict__ outH)
{
    long row = blockIdx.x;
    const float* x = X + row * HID;
    const float* y = Y + row * HID;
    int tid = threadIdx.x;
    float v[4]; float s = 0.f, s2 = 0.f;
    #pragma unroll
    for (int i = 0; i < 4; i++) {
        v[i] = x[tid + 128 * i] + y[tid + 128 * i];
        s += v[i]; s2 += v[i] * v[i];
    }
    __shared__ float rs[4], rs2[4];
    #pragma unroll
    for (int o = 16; o > 0; o >>= 1) {
        s  += __shfl_xor_sync(~0u, s, o);
        s2 += __shfl_xor_sync(~0u, s2, o);
    }
    if ((tid & 31) == 0) { rs[tid >> 5] = s; rs2[tid >> 5] = s2; }
    __syncthreads();
    s  = rs[0] + rs[1] + rs[2] + rs[3];
    s2 = rs2[0] + rs2[1] + rs2[2] + rs2[3];
    float mean = s * (1.f / HID);
    float var  = s2 * (1.f / HID) - mean * mean;
    float inv  = rsqrtf(var + 1e-5f);
    #pragma unroll
    for (int i = 0; i < 4; i++) {
        int c = tid + 128 * i;
        float val = (v[i] - mean) * inv * g[c] + b[c];
        if (outF) outF[row * HID + c] = val;
        if (outH) outH[row * HID + c] = __float2half(val);
    }
}

// ---------------- host orchestration ----------------
static inline dim3 G(int M, int N) { return dim3(N >> 7, M >> 7); }

extern "C" void kernel_launch(void* const* d_in, const int* in_sizes, int n_in,
                              void* d_out, int out_size)
{
    (void)in_sizes; (void)n_in; (void)out_size;
    const float* x_in  = (const float*)d_in[0];
    const float* slow  = (const float*)d_in[1];
    const float* Wq_in = (const float*)d_in[3];
    const float* bq_in = (const float*)d_in[4];
    const float* Wm  = (const float*)d_in[5];
    const float* bm  = (const float*)d_in[6];
    const float* Wq  = (const float*)d_in[7];
    const float* bq  = (const float*)d_in[8];
    const float* Wk  = (const float*)d_in[9];
    const float* bk  = (const float*)d_in[10];
    const float* Wv  = (const float*)d_in[11];
    const float* bv  = (const float*)d_in[12];
    const float* Wo  = (const float*)d_in[13];
    const float* bo  = (const float*)d_in[14];
    const float* g1  = (const float*)d_in[15];
    const float* be1 = (const float*)d_in[16];
    const float* W1  = (const float*)d_in[17];
    const float* b1  = (const float*)d_in[18];
    const float* W2  = (const float*)d_in[19];
    const float* b2  = (const float*)d_in[20];
    const float* g2  = (const float*)d_in[21];
    const float* be2 = (const float*)d_in[22];
    const float* M1  = (const float*)d_in[23];
    const float* bm1 = (const float*)d_in[24];
    const float* M2  = (const float*)d_in[25];
    const float* bm2 = (const float*)d_in[26];
    float* out = (float*)d_out;

    float *qinF, *q, *kvP, *o, *h, *bkv;
    __half *slowH, *kvH, *qinH, *qH, *kH, *vtH, *oH, *hH, *ffH, *h2H;
    __half *wqinT, *wqT, *wkvT, *woT, *w1T, *w2T, *m1T, *m2T;
    cudaGetSymbolAddress((void**)&qinF, g_qin);
    cudaGetSymbolAddress((void**)&q,    g_q);
    cudaGetSymbolAddress((void**)&kvP,  g_kvP);
    cudaGetSymbolAddress((void**)&o,    g_o);
    cudaGetSymbolAddress((void**)&h,    g_h);
    cudaGetSymbolAddress((void**)&bkv,  g_bkv);
    cudaGetSymbolAddress((void**)&slowH, g_slowH);
    cudaGetSymbolAddress((void**)&kvH,   g_kvH);
    cudaGetSymbolAddress((void**)&qinH,  g_qinH);
    cudaGetSymbolAddress((void**)&qH,    g_qH);
    cudaGetSymbolAddress((void**)&kH,    g_kH);
    cudaGetSymbolAddress((void**)&vtH,   g_vtH);
    cudaGetSymbolAddress((void**)&oH,    g_oH);
    cudaGetSymbolAddress((void**)&hH,    g_hH);
    cudaGetSymbolAddress((void**)&ffH,   g_ffH);
    cudaGetSymbolAddress((void**)&h2H,   g_h2H);
    cudaGetSymbolAddress((void**)&wqinT, g_wqinT);
    cudaGetSymbolAddress((void**)&wqT,   g_wqT);
    cudaGetSymbolAddress((void**)&wkvT,  g_wkvT);
    cudaGetSymbolAddress((void**)&woT,   g_woT);
    cudaGetSymbolAddress((void**)&w1T,   g_w1T);
    cudaGetSymbolAddress((void**)&w2T,   g_w2T);
    cudaGetSymbolAddress((void**)&m1T,   g_m1T);
    cudaGetSymbolAddress((void**)&m2T,   g_m2T);

    static int attr_set = 0;
    if (!attr_set) {
        cudaFuncSetAttribute(tgemm, cudaFuncAttributeMaxDynamicSharedMemorySize, GEMM_SMEM);
        cudaFuncSetAttribute(flash_attn, cudaFuncAttributeMaxDynamicSharedMemorySize, FLASH_SMEM);
        attr_set = 1;
    }

    TransArgs ta;
    ta.d[0] = { Wq_in, wqinT,            896,  512,    0 };
    ta.d[1] = { Wq,    wqT,              512,  512,  448 };
    ta.d[2] = { Wk,    wkvT,            1024,  512,  704 };   // k rows 0-511
    ta.d[3] = { Wv,    wkvT + 512*1024, 1024,  512, 1216 };   // v rows 512-1023
    ta.d[4] = { Wo,    woT,              512,  512, 1728 };
    ta.d[5] = { W1,    w1T,              512, 1024, 1984 };
    ta.d[6] = { W2,    w2T,             1024,  512, 2496 };
    ta.d[7] = { M1,    m1T,              512, 1024, 3008 };
    ta.d[8] = { M2,    m2T,             1024,  896, 3520 };   // total 4416

    dim3 tb(32, 8);
    // launches 0..4
    transpose_all<<<4416, tb>>>(ta);
    to_half<<<(int)(((long)MQ * DQ / 8 + 255) / 256), 256>>>(slow, slowH, (long)MQ * DQ);
    kvmap<<<(MKV * 256 + 255) / 256, 256>>>(x_in, Wm, bm, kvH);
    concat_bias<<<4, 256>>>(bk, bv, bkv);
    tgemm<<<G(MQ, HID), 256, GEMM_SMEM>>>(slowH, wqinT, bq_in, qinF, qinH,
        MQ, HID, DQ, DQ, DQ, HID, 0);
    // 5: merged k|v projection (grid 256)   <- ncu profile target
    tgemm<<<G(MKV, 1024), 256, GEMM_SMEM>>>(kvH, wkvT, bkv, kvP, (__half*)0,
        MKV, 1024, EMB, EMB, EMB, 1024, 0);
    tgemm<<<G(MQ, HID), 256, GEMM_SMEM>>>(qinH, wqT, bq, q, (__half*)0,
        MQ, HID, HID, HID, HID, HID, 0);
    {
        long tot = (long)MQ * NH * 64 + (long)MKV * NH * 64;
        rope_all<<<(int)((tot + 255) / 256), 256>>>(q, qH, kvP, kH);
    }
    vtrans<<<dim3(NKT/32, HD/32, BB * NH), tb>>>(kvP, vtH);
    flash_attn<<<dim3(NQT / 128, BB * NH), 256, FLASH_SMEM>>>(qH, kH, vtH, oH);
    tgemm<<<G(MQ, HID), 256, GEMM_SMEM>>>(oH, woT, bo, q, (__half*)0,
        MQ, HID, HID, HID, HID, HID, 0);
    add_ln<<<MQ, 128>>>(qinF, q, g1, be1, h, hH);
    tgemm<<<G(MQ, FFD), 256, GEMM_SMEM>>>(hH, w1T, b1, (float*)0, ffH,
        MQ, FFD, HID, HID, HID, FFD, 1);
    tgemm<<<G(MQ, HID), 256, GEMM_SMEM>>>(ffH, w2T, b2, o, (__half*)0,
        MQ, HID, FFD, FFD, FFD, HID, 0);
    add_ln<<<MQ, 128>>>(h, o, g2, be2, (float*)0, h2H);
    tgemm<<<G(MQ, FFD), 256, GEMM_SMEM>>>(h2H, m1T, bm1, (float*)0, ffH,
        MQ, FFD, HID, HID, HID, FFD, 1);
    tgemm<<<G(MQ, OUTD), 256, GEMM_SMEM>>>(ffH, m2T, bm2, out, (__half*)0,
        MQ, OUTD, FFD, FFD, FFD, OUTD, 0);
}